// round 13
// baseline (speedup 1.0000x reference)
#include <cuda_runtime.h>
#include <cuda_bf16.h>
#include <math.h>
#include <stdint.h>
#include <stddef.h>

#define NMESH 10242
#define NGRID 65160
#define NEDGES 195480
#define DDIM 512
#define NOUT 471

// padded row counts (multiple of 128 so cp.async tiles stay in-bounds)
#define E_PAD 195584
#define G_PAD 65280
#define M_PAD 10368

// GEMM tiling: CTA 128x128, K-chunk 32 bf16; 8 warps of 64x32; 2 CTAs/SM
#define BM 128
#define BN 128
#define BK 32
#define NTHR 256

#define SMROW 80
#define SM_ALO 10240
#define SM_BHI 20480
#define SM_BLO 30720
#define SM_BUFSZ 40960
#define SM_BUFS 1024
#define SM_TOTAL (SM_BUFS + 2 * SM_BUFSZ)

// ---------------------------------------------------------------------------
// Scratch (device globals — no dynamic allocation allowed)
// ---------------------------------------------------------------------------
__device__ __nv_bfloat16 g_xhi[(size_t)E_PAD * DDIM];  // ping
__device__ __nv_bfloat16 g_xlo[(size_t)E_PAD * DDIM];
__device__ __nv_bfloat16 g_yhi[(size_t)E_PAD * DDIM];  // pong
__device__ __nv_bfloat16 g_ylo[(size_t)E_PAD * DDIM];
__device__ __nv_bfloat16 g_ghi[(size_t)G_PAD * DDIM];  // grid pre-split
__device__ __nv_bfloat16 g_glo[(size_t)G_PAD * DDIM];
__device__ __nv_bfloat16 g_mhi[(size_t)M_PAD * DDIM];  // mesh pre-split
__device__ __nv_bfloat16 g_mlo[(size_t)M_PAD * DDIM];
__device__ float g_e0f[(size_t)NEDGES * DDIM];         // e0 fp32 (residual use)
__device__ float g_agg[(size_t)NGRID * DDIM];
__device__ float g_um[(size_t)NMESH * DDIM];
__device__ float g_ug[(size_t)NGRID * DDIM];
__device__ float g_zbias[DDIM];

// Pre-transposed / pre-split weights: [N=512 rows][K] row-major bf16
#define OFF_EMBW1  0u
#define OFF_WM     262144u
#define OFF_WG     524288u
#define OFF_WE     786432u
#define OFF_EDGEW1 1048576u
#define OFF_NODEW0 1310720u   /* K=1024 */
#define OFF_NODEW1 1835008u
#define OFF_OUTW0  2097152u
#define OFF_OUTW1  2359296u   /* padded from 471 cols */
#define WT_TOTAL   2621440u
__device__ __nv_bfloat16 g_wThi[WT_TOTAL];
__device__ __nv_bfloat16 g_wTlo[WT_TOTAL];

// ---------------------------------------------------------------------------
// Helpers
// ---------------------------------------------------------------------------
__device__ __forceinline__ uint32_t smem_u32(const void* p) {
    uint32_t a;
    asm("{ .reg .u64 t; cvta.to.shared.u64 t, %1; cvt.u32.u64 %0, t; }"
        : "=r"(a) : "l"(p));
    return a;
}
__device__ __forceinline__ void cpasync16(uint32_t dst, const void* src) {
    asm volatile("cp.async.cg.shared.global [%0], [%1], 16;"
                 :: "r"(dst), "l"(src) : "memory");
}
__device__ __forceinline__ void cp_commit() {
    asm volatile("cp.async.commit_group;" ::: "memory");
}
__device__ __forceinline__ void cp_wait_all() {
    asm volatile("cp.async.wait_group 0;" ::: "memory");
}
__device__ __forceinline__ void ldsm4(uint32_t* r, uint32_t addr) {
    asm volatile("ldmatrix.sync.aligned.m8n8.x4.shared.b16 {%0,%1,%2,%3}, [%4];"
                 : "=r"(r[0]), "=r"(r[1]), "=r"(r[2]), "=r"(r[3]) : "r"(addr));
}
__device__ __forceinline__ void mma_bf16(float* c, const uint32_t* a, const uint32_t* b) {
    asm volatile(
        "mma.sync.aligned.m16n8k16.row.col.f32.bf16.bf16.f32 "
        "{%0,%1,%2,%3}, {%4,%5,%6,%7}, {%8,%9}, {%0,%1,%2,%3};"
        : "+f"(c[0]), "+f"(c[1]), "+f"(c[2]), "+f"(c[3])
        : "r"(a[0]), "r"(a[1]), "r"(a[2]), "r"(a[3]), "r"(b[0]), "r"(b[1]));
}
__device__ __forceinline__ void split1(float v, uint16_t& h, uint16_t& l) {
    __nv_bfloat16 hb = __float2bfloat16(v);
    __nv_bfloat16 lb = __float2bfloat16(v - __bfloat162float(hb));
    h = __bfloat16_as_ushort(hb);
    l = __bfloat16_as_ushort(lb);
}
__device__ __forceinline__ float silu_f(float v) {
    return __fdividef(v, 1.0f + __expf(-v));
}

// ---------------------------------------------------------------------------
// Small kernels
// ---------------------------------------------------------------------------
// h1 = silu(attrs @ emb_w0 + emb_b0), written directly as bf16 hi/lo pairs
__global__ void emb_l1_pack(const float* __restrict__ attrs,
                            const float* __restrict__ w0,
                            const float* __restrict__ b0,
                            __nv_bfloat16* __restrict__ hi,
                            __nv_bfloat16* __restrict__ lo) {
    size_t idx = (size_t)blockIdx.x * blockDim.x + threadIdx.x;
    if (idx >= (size_t)NEDGES * 256) return;
    int r = (int)(idx >> 8);
    int c2 = (int)(idx & 255) * 2;
    float v0 = b0[c2], v1 = b0[c2 + 1];
#pragma unroll
    for (int j = 0; j < 4; j++) {
        float a = attrs[r * 4 + j];
        v0 = fmaf(a, w0[j * DDIM + c2], v0);
        v1 = fmaf(a, w0[j * DDIM + c2 + 1], v1);
    }
    v0 = silu_f(v0);
    v1 = silu_f(v1);
    uint16_t h0, l0, h1, l1;
    split1(v0, h0, l0);
    split1(v1, h1, l1);
    size_t o = (size_t)r * DDIM + c2;
    *(uint32_t*)(hi + o) = (uint32_t)h0 | ((uint32_t)h1 << 16);
    *(uint32_t*)(lo + o) = (uint32_t)l0 | ((uint32_t)l1 << 16);
}

// fp32 array -> bf16 hi/lo pair (2 elements per thread, packed stores)
__global__ void split_pack(const float* __restrict__ src,
                           __nv_bfloat16* __restrict__ hi,
                           __nv_bfloat16* __restrict__ lo, size_t n2) {
    size_t i = (size_t)blockIdx.x * blockDim.x + threadIdx.x;
    if (i >= n2) return;
    float v0 = src[2 * i], v1 = src[2 * i + 1];
    uint16_t h0, l0, h1, l1;
    split1(v0, h0, l0);
    split1(v1, h1, l1);
    *(uint32_t*)(hi + 2 * i) = (uint32_t)h0 | ((uint32_t)h1 << 16);
    *(uint32_t*)(lo + 2 * i) = (uint32_t)l0 | ((uint32_t)l1 << 16);
}

__global__ void zero_kernel(float4* __restrict__ p, size_t n4) {
    size_t i = (size_t)blockIdx.x * blockDim.x + threadIdx.x;
    if (i < n4) p[i] = make_float4(0.f, 0.f, 0.f, 0.f);
}

// W [K, Nsrc] fp32 row-major -> WT_hi/lo [512 rows][K] bf16, rows >= Nsrc zero
__global__ void prep_wT(const float* __restrict__ W, int K, int Nsrc,
                        __nv_bfloat16* __restrict__ hi,
                        __nv_bfloat16* __restrict__ lo) {
    int idx = blockIdx.x * blockDim.x + threadIdx.x;
    if (idx >= 512 * K) return;
    int n = idx / K;
    int k = idx - n * K;
    float v = (n < Nsrc) ? W[(size_t)k * Nsrc + n] : 0.f;
    __nv_bfloat16 h = __float2bfloat16(v);
    hi[idx] = h;
    lo[idx] = __float2bfloat16(v - __bfloat162float(h));
}

// ---------------------------------------------------------------------------
// HMMA fused GEMM (128x128 CTA, 8 warps of 64x32, 2 CTAs/SM)
// A is pre-split bf16 hi/lo in global; pure cp.async mainloop.
//   CONCAT: K=1024, cols >=512 from A2 pair
//   ACT silu | RES += resid fp32 | SCAT atomicAdd agg[dst[r]] |
//   GADD += gUm[src[r]] + gUg[dst[r]] | WF write fp32 C | WH write hi/lo pair
// ---------------------------------------------------------------------------
template <bool CONCAT, bool ACT, bool RES, bool SCAT, bool GADD, bool WF, bool WH>
__global__ void __launch_bounds__(NTHR, 2) gemm_mm(
    const __nv_bfloat16* __restrict__ A1hi, const __nv_bfloat16* __restrict__ A1lo,
    const __nv_bfloat16* __restrict__ A2hi, const __nv_bfloat16* __restrict__ A2lo,
    const __nv_bfloat16* __restrict__ BThi, const __nv_bfloat16* __restrict__ BTlo,
    const float* __restrict__ bias,
    const float* __restrict__ resid,
    float* __restrict__ C, int ldc, int Nc,
    __nv_bfloat16* __restrict__ Chi, __nv_bfloat16* __restrict__ Clo,
    const float* __restrict__ gUm, const float* __restrict__ gUg,
    float* __restrict__ gagg,
    const int* __restrict__ srcIdx, const int* __restrict__ dstIdx,
    int M, int K) {
    extern __shared__ char sm[];
    const uint32_t smb = smem_u32(sm);
    const int tid = threadIdx.x;
    const int wid = tid >> 5;
    const int lane = tid & 31;
    const int bm = blockIdx.y * BM;
    const int bn = blockIdx.x * BN;
    const int mbase = (wid >> 2) * 64;
    const int nbase = (wid & 3) * 32;

    int* sSrc = (int*)(sm);
    int* sDst = (int*)(sm + 512);
    if (GADD) {
        for (int i = tid; i < BM; i += NTHR) {
            int r = bm + i;
            sSrc[i] = (r < M) ? srcIdx[r] : 0;
            sDst[i] = (r < M) ? dstIdx[r] : 0;
        }
        __syncthreads();
    }

    // ---- cp.async A hi/lo (pre-split bf16, rows padded) ----
    auto cpA = [&](int c, int buf) {
        int k0 = c * BK;
        uint32_t Ab = smb + SM_BUFS + buf * SM_BUFSZ;
#pragma unroll
        for (int it = 0; it < 2; ++it) {
            int idx = it * NTHR + tid;   // 0..511
            int row = idx >> 2;          // 0..127
            int ch = idx & 3;
            int gcol = k0 + ch * 8;
            const __nv_bfloat16 *ph, *pl;
            if (CONCAT && gcol >= 512) {
                size_t o = (size_t)(bm + row) * DDIM + (gcol - 512);
                ph = A2hi + o; pl = A2lo + o;
            } else {
                size_t o = (size_t)(bm + row) * DDIM + gcol;
                ph = A1hi + o; pl = A1lo + o;
            }
            uint32_t doff = (uint32_t)(row * SMROW + ch * 16);
            cpasync16(Ab + doff, ph);
            cpasync16(Ab + SM_ALO + doff, pl);
        }
    };
    // ---- cp.async B hi/lo ----
    auto cpB = [&](int c, int buf) {
        int k0 = c * BK;
        uint32_t Bb = smb + SM_BUFS + buf * SM_BUFSZ + SM_BHI;
#pragma unroll
        for (int it = 0; it < 2; ++it) {
            int idx = it * NTHR + tid;
            int row = idx >> 2;
            int ch = idx & 3;
            uint32_t doff = (uint32_t)(row * SMROW + ch * 16);
            size_t g = (size_t)(bn + row) * K + k0 + ch * 8;
            cpasync16(Bb + doff, BThi + g);
            cpasync16(Bb + (SM_BLO - SM_BHI) + doff, BTlo + g);
        }
    };

    float acc[4][4][4];
#pragma unroll
    for (int i = 0; i < 4; i++)
#pragma unroll
        for (int j = 0; j < 4; j++)
#pragma unroll
            for (int e = 0; e < 4; e++) acc[i][j][e] = 0.f;

    const int NC = K / BK;

    cpA(0, 0);
    cpB(0, 0);
    cp_commit();

    for (int c = 0; c < NC; ++c) {
        const int buf = c & 1;
        cp_wait_all();
        __syncthreads();
        if (c + 1 < NC) {
            cpA(c + 1, buf ^ 1);
            cpB(c + 1, buf ^ 1);
            cp_commit();
        }
        const uint32_t Ab = smb + SM_BUFS + buf * SM_BUFSZ;
        const uint32_t Bb = Ab + SM_BHI;
#pragma unroll
        for (int kh = 0; kh < 2; ++kh) {
            const uint32_t acol = (uint32_t)(kh * 32 + ((lane >> 4) << 4));
            const uint32_t bcol = (uint32_t)(kh * 32 + ((lane >> 3) & 1) * 16);
            const uint32_t brow = (uint32_t)(nbase + ((lane >> 4) << 3) + (lane & 7));
            uint32_t af[4][4], bh[2][4], bl[2][4];
#pragma unroll
            for (int j2 = 0; j2 < 2; ++j2) {
                uint32_t ba = Bb + (brow + j2 * 16) * SMROW + bcol;
                ldsm4(bh[j2], ba);
                ldsm4(bl[j2], ba + (SM_BLO - SM_BHI));
            }
            // pass 1: A-hi x (B-hi, B-lo)
#pragma unroll
            for (int i = 0; i < 4; ++i)
                ldsm4(af[i], Ab + (uint32_t)((mbase + i * 16 + (lane & 15)) * SMROW) + acol);
#pragma unroll
            for (int i = 0; i < 4; ++i)
#pragma unroll
                for (int j2 = 0; j2 < 2; ++j2) {
                    mma_bf16(acc[i][2 * j2],     af[i], &bh[j2][0]);
                    mma_bf16(acc[i][2 * j2 + 1], af[i], &bh[j2][2]);
                    mma_bf16(acc[i][2 * j2],     af[i], &bl[j2][0]);
                    mma_bf16(acc[i][2 * j2 + 1], af[i], &bl[j2][2]);
                }
            // pass 2: A-lo x B-hi
#pragma unroll
            for (int i = 0; i < 4; ++i)
                ldsm4(af[i], Ab + SM_ALO + (uint32_t)((mbase + i * 16 + (lane & 15)) * SMROW) + acol);
#pragma unroll
            for (int i = 0; i < 4; ++i)
#pragma unroll
                for (int j2 = 0; j2 < 2; ++j2) {
                    mma_bf16(acc[i][2 * j2],     af[i], &bh[j2][0]);
                    mma_bf16(acc[i][2 * j2 + 1], af[i], &bh[j2][2]);
                }
        }
    }

    // ---- epilogue ----
    const int gid = lane >> 2, tig = lane & 3;
#pragma unroll
    for (int i = 0; i < 4; ++i) {
#pragma unroll
        for (int half = 0; half < 2; ++half) {
            int lr = mbase + i * 16 + gid + half * 8;
            int r = bm + lr;
            if (r >= M) continue;
            int dd = 0;
            if (SCAT) dd = dstIdx[r];
#pragma unroll
            for (int j = 0; j < 4; ++j) {
                int n0 = bn + nbase + j * 8 + tig * 2;
                float v0 = acc[i][j][half * 2];
                float v1 = acc[i][j][half * 2 + 1];
                v0 += bias[n0];
                v1 += (n0 + 1 < Nc) ? bias[n0 + 1] : 0.f;
                if (GADD) {
                    const float* um = gUm + (size_t)sSrc[lr] * DDIM;
                    const float* ug = gUg + (size_t)sDst[lr] * DDIM;
                    v0 += um[n0] + ug[n0];
                    v1 += um[n0 + 1] + ug[n0 + 1];
                }
                if (ACT) { v0 = silu_f(v0); v1 = silu_f(v1); }
                if (RES) {
                    const float* rr = resid + (size_t)r * DDIM;
                    v0 += rr[n0];
                    v1 += rr[n0 + 1];
                }
                if (SCAT) {
                    float* ag = gagg + (size_t)dd * DDIM;
                    atomicAdd(&ag[n0], v0);
                    atomicAdd(&ag[n0 + 1], v1);
                }
                if (WF) {
                    if (n0 < Nc)     C[(size_t)r * ldc + n0] = v0;
                    if (n0 + 1 < Nc) C[(size_t)r * ldc + n0 + 1] = v1;
                }
                if (WH) {
                    uint16_t h0, l0, h1, l1;
                    split1(v0, h0, l0);
                    split1(v1, h1, l1);
                    size_t o = (size_t)r * DDIM + n0;
                    *(uint32_t*)(Chi + o) = (uint32_t)h0 | ((uint32_t)h1 << 16);
                    *(uint32_t*)(Clo + o) = (uint32_t)l0 | ((uint32_t)l1 << 16);
                }
            }
        }
    }
}

// ---------------------------------------------------------------------------
// Launch
// ---------------------------------------------------------------------------
#define SETSM(k) cudaFuncSetAttribute(k, cudaFuncAttributeMaxDynamicSharedMemorySize, SM_TOTAL)

extern "C" void kernel_launch(void* const* d_in, const int* in_sizes, int n_in,
                              void* d_out, int out_size) {
    (void)in_sizes; (void)n_in; (void)out_size;

    const float* mesh    = (const float*)d_in[0];
    const float* grid    = (const float*)d_in[1];
    const float* attrs   = (const float*)d_in[2];
    const int*   esrc    = (const int*)d_in[3];
    const int*   edst    = (const int*)d_in[4];
    const float* emb_w0  = (const float*)d_in[5];
    const float* emb_b0  = (const float*)d_in[6];
    const float* emb_w1  = (const float*)d_in[7];
    const float* emb_b1  = (const float*)d_in[8];
    const float* edge_w0 = (const float*)d_in[9];
    const float* edge_b0 = (const float*)d_in[10];
    const float* edge_w1 = (const float*)d_in[11];
    const float* edge_b1 = (const float*)d_in[12];
    const float* node_w0 = (const float*)d_in[13];
    const float* node_b0 = (const float*)d_in[14];
    const float* node_w1 = (const float*)d_in[15];
    const float* node_b1 = (const float*)d_in[16];
    const float* out_w0  = (const float*)d_in[17];
    const float* out_b0  = (const float*)d_in[18];
    const float* out_w1  = (const float*)d_in[19];
    const float* out_b1  = (const float*)d_in[20];
    float* out = (float*)d_out;

    __nv_bfloat16 *pXhi, *pXlo, *pYhi, *pYlo, *pGhi, *pGlo, *pMhi, *pMlo, *pWThi, *pWTlo;
    float *pE0f, *pAgg, *pUm, *pUg, *pZb;
    cudaGetSymbolAddress((void**)&pXhi, g_xhi);
    cudaGetSymbolAddress((void**)&pXlo, g_xlo);
    cudaGetSymbolAddress((void**)&pYhi, g_yhi);
    cudaGetSymbolAddress((void**)&pYlo, g_ylo);
    cudaGetSymbolAddress((void**)&pGhi, g_ghi);
    cudaGetSymbolAddress((void**)&pGlo, g_glo);
    cudaGetSymbolAddress((void**)&pMhi, g_mhi);
    cudaGetSymbolAddress((void**)&pMlo, g_mlo);
    cudaGetSymbolAddress((void**)&pE0f, g_e0f);
    cudaGetSymbolAddress((void**)&pAgg, g_agg);
    cudaGetSymbolAddress((void**)&pUm, g_um);
    cudaGetSymbolAddress((void**)&pUg, g_ug);
    cudaGetSymbolAddress((void**)&pZb, g_zbias);
    cudaGetSymbolAddress((void**)&pWThi, g_wThi);
    cudaGetSymbolAddress((void**)&pWTlo, g_wTlo);

    // instantiations: <CONCAT,ACT,RES,SCAT,GADD,WF,WH>
    SETSM((gemm_mm<false,false,false,false,false,true, true >)); // e0
    SETSM((gemm_mm<false,false,false,false,false,true, false>)); // Um/Ug/out2
    SETSM((gemm_mm<false,true, false,false,true, false,true >)); // edge h (gather-add)
    SETSM((gemm_mm<false,false,true, true, false,false,false>)); // scatter
    SETSM((gemm_mm<true, true, false,false,false,false,true >)); // node1 concat
    SETSM((gemm_mm<false,false,true, false,false,false,true >)); // node2 resid
    SETSM((gemm_mm<false,true, false,false,false,false,true >)); // out1

    const int E = NEDGES, G = NGRID;
    dim3 gridE(4, E_PAD / BM);
    dim3 gridG(4, G_PAD / BM);
    dim3 gridM(4, M_PAD / BM);

    // #0: h1 = silu(attrs@emb_w0 + b0) -> X (bf16 hi/lo)
    {
        size_t tot = (size_t)E * 256;
        emb_l1_pack<<<(unsigned)((tot + 255) / 256), 256>>>(attrs, emb_w0, emb_b0, pXhi, pXlo);
    }
    // #1: prep emb_w1
    prep_wT<<<(512 * 512 + 255) / 256, 256>>>(emb_w1, 512, 512, pWThi + OFF_EMBW1, pWTlo + OFF_EMBW1);
    // #2: zero bias
    zero_kernel<<<1, 128>>>((float4*)pZb, DDIM / 4);
    // #3 (ncu capture slot): e0 = h1 @ emb_w1 + b1 -> e0f (fp32) + Y (bf16)
    gemm_mm<false,false,false,false,false,true,true><<<gridE, NTHR, SM_TOTAL>>>(
        pXhi, pXlo, nullptr, nullptr, pWThi + OFF_EMBW1, pWTlo + OFF_EMBW1,
        emb_b1, nullptr, pE0f, DDIM, DDIM, pYhi, pYlo,
        nullptr, nullptr, nullptr, nullptr, nullptr, E, DDIM);
    // #4-#5: split grid / mesh inputs
    split_pack<<<(unsigned)(((size_t)G * 256 + 255) / 256), 256>>>(grid, pGhi, pGlo, (size_t)G * 256);
    split_pack<<<(unsigned)(((size_t)NMESH * 256 + 255) / 256), 256>>>(mesh, pMhi, pMlo, (size_t)NMESH * 256);
    // #6-#8: prep W_e, W_m, W_g
    prep_wT<<<(512 * 512 + 255) / 256, 256>>>(edge_w0 + (size_t)1024 * 512, 512, 512, pWThi + OFF_WE, pWTlo + OFF_WE);
    prep_wT<<<(512 * 512 + 255) / 256, 256>>>(edge_w0, 512, 512, pWThi + OFF_WM, pWTlo + OFF_WM);
    prep_wT<<<(512 * 512 + 255) / 256, 256>>>(edge_w0 + (size_t)512 * 512, 512, 512, pWThi + OFF_WG, pWTlo + OFF_WG);
    // #9: U_m = mesh @ W_m (fp32)
    gemm_mm<false,false,false,false,false,true,false><<<gridM, NTHR, SM_TOTAL>>>(
        pMhi, pMlo, nullptr, nullptr, pWThi + OFF_WM, pWTlo + OFF_WM,
        pZb, nullptr, pUm, DDIM, DDIM, nullptr, nullptr,
        nullptr, nullptr, nullptr, nullptr, nullptr, NMESH, DDIM);
    // #10: U_g = grid @ W_g (fp32)
    gemm_mm<false,false,false,false,false,true,false><<<gridG, NTHR, SM_TOTAL>>>(
        pGhi, pGlo, nullptr, nullptr, pWThi + OFF_WG, pWTlo + OFF_WG,
        pZb, nullptr, pUg, DDIM, DDIM, nullptr, nullptr,
        nullptr, nullptr, nullptr, nullptr, nullptr, G, DDIM);
    // #11: agg = 0
    {
        size_t n4 = (size_t)G * DDIM / 4;
        zero_kernel<<<(unsigned)((n4 + 255) / 256), 256>>>((float4*)pAgg, n4);
    }
    // #12: h = silu(e0@W_e + edge_b0 + Um[src] + Ug[dst]) -> X
    gemm_mm<false,true,false,false,true,false,true><<<gridE, NTHR, SM_TOTAL>>>(
        pYhi, pYlo, nullptr, nullptr, pWThi + OFF_WE, pWTlo + OFF_WE,
        edge_b0, nullptr, nullptr, DDIM, DDIM, pXhi, pXlo,
        pUm, pUg, nullptr, esrc, edst, E, DDIM);
    // #13: prep edge_w1
    prep_wT<<<(512 * 512 + 255) / 256, 256>>>(edge_w1, 512, 512, pWThi + OFF_EDGEW1, pWTlo + OFF_EDGEW1);
    // #14: agg[dst] += e0 + h@edge_w1 + edge_b1
    gemm_mm<false,false,true,true,false,false,false><<<gridE, NTHR, SM_TOTAL>>>(
        pXhi, pXlo, nullptr, nullptr, pWThi + OFF_EDGEW1, pWTlo + OFF_EDGEW1,
        edge_b1, pE0f, nullptr, DDIM, DDIM, nullptr, nullptr,
        nullptr, nullptr, pAgg, nullptr, edst, E, DDIM);
    // #15: split agg -> Y
    split_pack<<<(unsigned)(((size_t)G * 256 + 255) / 256), 256>>>(pAgg, pYhi, pYlo, (size_t)G * 256);
    // #16: prep node_w0 (K=1024)
    prep_wT<<<(512 * 1024 + 255) / 256, 256>>>(node_w0, 1024, 512, pWThi + OFF_NODEW0, pWTlo + OFF_NODEW0);
    // #17: h = silu(concat(grid, agg)@node_w0 + node_b0) -> X
    gemm_mm<true,true,false,false,false,false,true><<<gridG, NTHR, SM_TOTAL>>>(
        pGhi, pGlo, pYhi, pYlo, pWThi + OFF_NODEW0, pWTlo + OFF_NODEW0,
        node_b0, nullptr, nullptr, DDIM, DDIM, pXhi, pXlo,
        nullptr, nullptr, nullptr, nullptr, nullptr, G, 2 * DDIM);
    // #18: prep node_w1
    prep_wT<<<(512 * 512 + 255) / 256, 256>>>(node_w1, 512, 512, pWThi + OFF_NODEW1, pWTlo + OFF_NODEW1);
    // #19: grid_new = grid + h@node_w1 + node_b1 -> Y (bf16 only)
    gemm_mm<false,false,true,false,false,false,true><<<gridG, NTHR, SM_TOTAL>>>(
        pXhi, pXlo, nullptr, nullptr, pWThi + OFF_NODEW1, pWTlo + OFF_NODEW1,
        node_b1, grid, nullptr, DDIM, DDIM, pYhi, pYlo,
        nullptr, nullptr, nullptr, nullptr, nullptr, G, DDIM);
    // #20: prep out_w0
    prep_wT<<<(512 * 512 + 255) / 256, 256>>>(out_w0, 512, 512, pWThi + OFF_OUTW0, pWTlo + OFF_OUTW0);
    // #21: h = silu(grid_new@out_w0 + out_b0) -> X
    gemm_mm<false,true,false,false,false,false,true><<<gridG, NTHR, SM_TOTAL>>>(
        pYhi, pYlo, nullptr, nullptr, pWThi + OFF_OUTW0, pWTlo + OFF_OUTW0,
        out_b0, nullptr, nullptr, DDIM, DDIM, pXhi, pXlo,
        nullptr, nullptr, nullptr, nullptr, nullptr, G, DDIM);
    // #22: prep out_w1 (padded 471 -> 512)
    prep_wT<<<(512 * 512 + 255) / 256, 256>>>(out_w1, 512, NOUT, pWThi + OFF_OUTW1, pWTlo + OFF_OUTW1);
    // #23: out = h@out_w1 + out_b1 (fp32, N-guard 471)
    gemm_mm<false,false,false,false,false,true,false><<<gridG, NTHR, SM_TOTAL>>>(
        pXhi, pXlo, nullptr, nullptr, pWThi + OFF_OUTW1, pWTlo + OFF_OUTW1,
        out_b1, nullptr, out, NOUT, NOUT, nullptr, nullptr,
        nullptr, nullptr, nullptr, nullptr, nullptr, G, DDIM);
}

// round 15
// speedup vs baseline: 1.5360x; 1.5360x over previous
#include <cuda_runtime.h>
#include <cuda_bf16.h>
#include <math.h>
#include <stdint.h>
#include <stddef.h>

#define NMESH 10242
#define NGRID 65160
#define NEDGES 195480
#define DDIM 512
#define NOUT 471

// padded row counts (multiple of 128 so cp.async tiles stay in-bounds)
#define E_PAD 195584
#define G_PAD 65280
#define M_PAD 10368

// GEMM tiling: CTA 128x128, K-chunk 32 bf16; 8 warps of 64x32; 2 CTAs/SM
#define BM 128
#define BN 128
#define BK 32
#define NTHR 256

#define SMROW 80
// A: 3-deep ring of (hi 10240 | lo 10240); B: 2-deep ring of (hi 10240 | lo 10240)
#define SM_HDR 1024
#define A_BUF 20480
#define B_BASE (SM_HDR + 3 * A_BUF)      /* 62464 */
#define B_BUF 20480
#define SM_TOTAL (SM_HDR + 3 * A_BUF + 2 * B_BUF)   /* 103424 */

// ---------------------------------------------------------------------------
// Scratch (device globals — no dynamic allocation allowed)
// ---------------------------------------------------------------------------
__device__ __nv_bfloat16 g_xhi[(size_t)E_PAD * DDIM];  // ping
__device__ __nv_bfloat16 g_xlo[(size_t)E_PAD * DDIM];
__device__ __nv_bfloat16 g_yhi[(size_t)E_PAD * DDIM];  // pong
__device__ __nv_bfloat16 g_ylo[(size_t)E_PAD * DDIM];
__device__ __nv_bfloat16 g_ghi[(size_t)G_PAD * DDIM];  // grid pre-split
__device__ __nv_bfloat16 g_glo[(size_t)G_PAD * DDIM];
__device__ __nv_bfloat16 g_mhi[(size_t)M_PAD * DDIM];  // mesh pre-split
__device__ __nv_bfloat16 g_mlo[(size_t)M_PAD * DDIM];
__device__ float g_e0f[(size_t)NEDGES * DDIM];         // e0 fp32 (residual use)
__device__ float g_agg[(size_t)NGRID * DDIM];
__device__ float g_um[(size_t)NMESH * DDIM];
__device__ float g_ug[(size_t)NGRID * DDIM];
__device__ float g_zbias[DDIM];

// Pre-transposed / pre-split weights: [N=512 rows][K] row-major bf16
#define OFF_EMBW1  0u
#define OFF_WM     262144u
#define OFF_WG     524288u
#define OFF_WE     786432u
#define OFF_EDGEW1 1048576u
#define OFF_NODEW0 1310720u   /* K=1024 */
#define OFF_NODEW1 1835008u
#define OFF_OUTW0  2097152u
#define OFF_OUTW1  2359296u   /* padded from 471 cols */
#define WT_TOTAL   2621440u
__device__ __nv_bfloat16 g_wThi[WT_TOTAL];
__device__ __nv_bfloat16 g_wTlo[WT_TOTAL];

// ---------------------------------------------------------------------------
// Helpers
// ---------------------------------------------------------------------------
__device__ __forceinline__ uint32_t smem_u32(const void* p) {
    uint32_t a;
    asm("{ .reg .u64 t; cvta.to.shared.u64 t, %1; cvt.u32.u64 %0, t; }"
        : "=r"(a) : "l"(p));
    return a;
}
__device__ __forceinline__ void cpasync16(uint32_t dst, const void* src) {
    asm volatile("cp.async.cg.shared.global [%0], [%1], 16;"
                 :: "r"(dst), "l"(src) : "memory");
}
__device__ __forceinline__ void cp_commit() {
    asm volatile("cp.async.commit_group;" ::: "memory");
}
__device__ __forceinline__ void cp_wait1() {
    asm volatile("cp.async.wait_group 1;" ::: "memory");
}
__device__ __forceinline__ void ldsm4(uint32_t* r, uint32_t addr) {
    asm volatile("ldmatrix.sync.aligned.m8n8.x4.shared.b16 {%0,%1,%2,%3}, [%4];"
                 : "=r"(r[0]), "=r"(r[1]), "=r"(r[2]), "=r"(r[3]) : "r"(addr));
}
__device__ __forceinline__ void mma_bf16(float* c, const uint32_t* a, const uint32_t* b) {
    asm volatile(
        "mma.sync.aligned.m16n8k16.row.col.f32.bf16.bf16.f32 "
        "{%0,%1,%2,%3}, {%4,%5,%6,%7}, {%8,%9}, {%0,%1,%2,%3};"
        : "+f"(c[0]), "+f"(c[1]), "+f"(c[2]), "+f"(c[3])
        : "r"(a[0]), "r"(a[1]), "r"(a[2]), "r"(a[3]), "r"(b[0]), "r"(b[1]));
}
__device__ __forceinline__ void split1(float v, uint16_t& h, uint16_t& l) {
    __nv_bfloat16 hb = __float2bfloat16(v);
    __nv_bfloat16 lb = __float2bfloat16(v - __bfloat162float(hb));
    h = __bfloat16_as_ushort(hb);
    l = __bfloat16_as_ushort(lb);
}
__device__ __forceinline__ float silu_f(float v) {
    return __fdividef(v, 1.0f + __expf(-v));
}

// ---------------------------------------------------------------------------
// Small kernels
// ---------------------------------------------------------------------------
__global__ void emb_l1_pack(const float* __restrict__ attrs,
                            const float* __restrict__ w0,
                            const float* __restrict__ b0,
                            __nv_bfloat16* __restrict__ hi,
                            __nv_bfloat16* __restrict__ lo) {
    size_t idx = (size_t)blockIdx.x * blockDim.x + threadIdx.x;
    if (idx >= (size_t)NEDGES * 256) return;
    int r = (int)(idx >> 8);
    int c2 = (int)(idx & 255) * 2;
    float v0 = b0[c2], v1 = b0[c2 + 1];
#pragma unroll
    for (int j = 0; j < 4; j++) {
        float a = attrs[r * 4 + j];
        v0 = fmaf(a, w0[j * DDIM + c2], v0);
        v1 = fmaf(a, w0[j * DDIM + c2 + 1], v1);
    }
    v0 = silu_f(v0);
    v1 = silu_f(v1);
    uint16_t h0, l0, h1, l1;
    split1(v0, h0, l0);
    split1(v1, h1, l1);
    size_t o = (size_t)r * DDIM + c2;
    *(uint32_t*)(hi + o) = (uint32_t)h0 | ((uint32_t)h1 << 16);
    *(uint32_t*)(lo + o) = (uint32_t)l0 | ((uint32_t)l1 << 16);
}

__global__ void split_pack(const float* __restrict__ src,
                           __nv_bfloat16* __restrict__ hi,
                           __nv_bfloat16* __restrict__ lo, size_t n2) {
    size_t i = (size_t)blockIdx.x * blockDim.x + threadIdx.x;
    if (i >= n2) return;
    float v0 = src[2 * i], v1 = src[2 * i + 1];
    uint16_t h0, l0, h1, l1;
    split1(v0, h0, l0);
    split1(v1, h1, l1);
    *(uint32_t*)(hi + 2 * i) = (uint32_t)h0 | ((uint32_t)h1 << 16);
    *(uint32_t*)(lo + 2 * i) = (uint32_t)l0 | ((uint32_t)l1 << 16);
}

__global__ void zero_kernel(float4* __restrict__ p, size_t n4) {
    size_t i = (size_t)blockIdx.x * blockDim.x + threadIdx.x;
    if (i < n4) p[i] = make_float4(0.f, 0.f, 0.f, 0.f);
}

__global__ void prep_wT(const float* __restrict__ W, int K, int Nsrc,
                        __nv_bfloat16* __restrict__ hi,
                        __nv_bfloat16* __restrict__ lo) {
    int idx = blockIdx.x * blockDim.x + threadIdx.x;
    if (idx >= 512 * K) return;
    int n = idx / K;
    int k = idx - n * K;
    float v = (n < Nsrc) ? W[(size_t)k * Nsrc + n] : 0.f;
    __nv_bfloat16 h = __float2bfloat16(v);
    hi[idx] = h;
    lo[idx] = __float2bfloat16(v - __bfloat162float(h));
}

// ---------------------------------------------------------------------------
// HMMA fused GEMM (128x128 CTA, 8 warps of 64x32, 2 CTAs/SM)
// A pre-split bf16 hi/lo via 3-deep cp.async ring; B 2-deep; wait_group 1.
//   CONCAT: K=1024, cols >=512 from A2 pair
//   ACT silu | RES += resid fp32 | SCAT atomicAdd agg[dst[r]] |
//   GADD += gUm[src[r]] + gUg[dst[r]] | WF write fp32 C | WH write hi/lo pair
// ---------------------------------------------------------------------------
template <bool CONCAT, bool ACT, bool RES, bool SCAT, bool GADD, bool WF, bool WH>
__global__ void __launch_bounds__(NTHR, 2) gemm_mm(
    const __nv_bfloat16* __restrict__ A1hi, const __nv_bfloat16* __restrict__ A1lo,
    const __nv_bfloat16* __restrict__ A2hi, const __nv_bfloat16* __restrict__ A2lo,
    const __nv_bfloat16* __restrict__ BThi, const __nv_bfloat16* __restrict__ BTlo,
    const float* __restrict__ bias,
    const float* __restrict__ resid,
    float* __restrict__ C, int ldc, int Nc,
    __nv_bfloat16* __restrict__ Chi, __nv_bfloat16* __restrict__ Clo,
    const float* __restrict__ gUm, const float* __restrict__ gUg,
    float* __restrict__ gagg,
    const int* __restrict__ srcIdx, const int* __restrict__ dstIdx,
    int M, int K) {
    extern __shared__ char sm[];
    const uint32_t smb = smem_u32(sm);
    const int tid = threadIdx.x;
    const int wid = tid >> 5;
    const int lane = tid & 31;
    const int bm = blockIdx.y * BM;
    const int bn = blockIdx.x * BN;
    const int mbase = (wid >> 2) * 64;
    const int nbase = (wid & 3) * 32;

    int* sSrc = (int*)(sm);
    int* sDst = (int*)(sm + 512);
    if (GADD) {
        for (int i = tid; i < BM; i += NTHR) {
            int r = bm + i;
            sSrc[i] = (r < M) ? srcIdx[r] : 0;
            sDst[i] = (r < M) ? dstIdx[r] : 0;
        }
        __syncthreads();
    }

    // ---- cp.async A hi/lo into ring buffer c%3 ----
    auto cpA = [&](int c) {
        int k0 = c * BK;
        uint32_t Ab = smb + SM_HDR + (c % 3) * A_BUF;
#pragma unroll
        for (int it = 0; it < 2; ++it) {
            int idx = it * NTHR + tid;   // 0..511
            int row = idx >> 2;          // 0..127
            int ch = idx & 3;
            int gcol = k0 + ch * 8;
            const __nv_bfloat16 *ph, *pl;
            if (CONCAT && gcol >= 512) {
                size_t o = (size_t)(bm + row) * DDIM + (gcol - 512);
                ph = A2hi + o; pl = A2lo + o;
            } else {
                size_t o = (size_t)(bm + row) * DDIM + gcol;
                ph = A1hi + o; pl = A1lo + o;
            }
            uint32_t doff = (uint32_t)(row * SMROW + ch * 16);
            cpasync16(Ab + doff, ph);
            cpasync16(Ab + 10240 + doff, pl);
        }
    };
    // ---- cp.async B hi/lo into ring buffer c%2 ----
    auto cpB = [&](int c) {
        int k0 = c * BK;
        uint32_t Bb = smb + B_BASE + (c % 2) * B_BUF;
#pragma unroll
        for (int it = 0; it < 2; ++it) {
            int idx = it * NTHR + tid;
            int row = idx >> 2;
            int ch = idx & 3;
            uint32_t doff = (uint32_t)(row * SMROW + ch * 16);
            size_t g = (size_t)(bn + row) * K + k0 + ch * 8;
            cpasync16(Bb + doff, BThi + g);
            cpasync16(Bb + 10240 + doff, BTlo + g);
        }
    };

    float acc[4][4][4];
#pragma unroll
    for (int i = 0; i < 4; i++)
#pragma unroll
        for (int j = 0; j < 4; j++)
#pragma unroll
            for (int e = 0; e < 4; e++) acc[i][j][e] = 0.f;

    const int NC = K / BK;

    // Prologue: group0 = {B0, A0}; group1 = {A1}
    cpB(0);
    cpA(0);
    cp_commit();
    if (1 < NC) cpA(1);
    cp_commit();

    for (int c = 0; c < NC; ++c) {
        // need: B(c) [committed in B-group of iter c-1], A(c) [A-group of iter c-2].
        // Last-committed group is always an A-group -> allow 1 outstanding.
        cp_wait1();
        __syncthreads();
        // B-group for c+1, then A-group for c+2 (order matters for wait_group 1)
        if (c + 1 < NC) cpB(c + 1);
        cp_commit();
        if (c + 2 < NC) cpA(c + 2);
        cp_commit();

        const uint32_t Ab = smb + SM_HDR + (c % 3) * A_BUF;
        const uint32_t Bb = smb + B_BASE + (c % 2) * B_BUF;
#pragma unroll
        for (int kh = 0; kh < 2; ++kh) {
            const uint32_t acol = (uint32_t)(kh * 32 + ((lane >> 4) << 4));
            const uint32_t bcol = (uint32_t)(kh * 32 + ((lane >> 3) & 1) * 16);
            const uint32_t brow = (uint32_t)(nbase + ((lane >> 4) << 3) + (lane & 7));
            uint32_t af[4][4], bh[2][4], bl[2][4];
#pragma unroll
            for (int j2 = 0; j2 < 2; ++j2) {
                uint32_t ba = Bb + (brow + j2 * 16) * SMROW + bcol;
                ldsm4(bh[j2], ba);
                ldsm4(bl[j2], ba + 10240);
            }
            // pass 1: A-hi x (B-hi, B-lo)
#pragma unroll
            for (int i = 0; i < 4; ++i)
                ldsm4(af[i], Ab + (uint32_t)((mbase + i * 16 + (lane & 15)) * SMROW) + acol);
#pragma unroll
            for (int i = 0; i < 4; ++i)
#pragma unroll
                for (int j2 = 0; j2 < 2; ++j2) {
                    mma_bf16(acc[i][2 * j2],     af[i], &bh[j2][0]);
                    mma_bf16(acc[i][2 * j2 + 1], af[i], &bh[j2][2]);
                    mma_bf16(acc[i][2 * j2],     af[i], &bl[j2][0]);
                    mma_bf16(acc[i][2 * j2 + 1], af[i], &bl[j2][2]);
                }
            // pass 2: A-lo x B-hi
#pragma unroll
            for (int i = 0; i < 4; ++i)
                ldsm4(af[i], Ab + 10240 + (uint32_t)((mbase + i * 16 + (lane & 15)) * SMROW) + acol);
#pragma unroll
            for (int i = 0; i < 4; ++i)
#pragma unroll
                for (int j2 = 0; j2 < 2; ++j2) {
                    mma_bf16(acc[i][2 * j2],     af[i], &bh[j2][0]);
                    mma_bf16(acc[i][2 * j2 + 1], af[i], &bh[j2][2]);
                }
        }
    }

    // ---- epilogue ----
    const int gid = lane >> 2, tig = lane & 3;
#pragma unroll
    for (int i = 0; i < 4; ++i) {
#pragma unroll
        for (int half = 0; half < 2; ++half) {
            int lr = mbase + i * 16 + gid + half * 8;
            int r = bm + lr;
            if (r >= M) continue;
            int dd = 0;
            if (SCAT) dd = dstIdx[r];
#pragma unroll
            for (int j = 0; j < 4; ++j) {
                int n0 = bn + nbase + j * 8 + tig * 2;
                float v0 = acc[i][j][half * 2];
                float v1 = acc[i][j][half * 2 + 1];
                v0 += bias[n0];
                v1 += (n0 + 1 < Nc) ? bias[n0 + 1] : 0.f;
                if (GADD) {
                    const float* um = gUm + (size_t)sSrc[lr] * DDIM;
                    const float* ug = gUg + (size_t)sDst[lr] * DDIM;
                    v0 += um[n0] + ug[n0];
                    v1 += um[n0 + 1] + ug[n0 + 1];
                }
                if (ACT) { v0 = silu_f(v0); v1 = silu_f(v1); }
                if (RES) {
                    const float* rr = resid + (size_t)r * DDIM;
                    v0 += rr[n0];
                    v1 += rr[n0 + 1];
                }
                if (SCAT) {
                    float* ag = gagg + (size_t)dd * DDIM;
                    atomicAdd(&ag[n0], v0);
                    atomicAdd(&ag[n0 + 1], v1);
                }
                if (WF) {
                    if (n0 < Nc)     C[(size_t)r * ldc + n0] = v0;
                    if (n0 + 1 < Nc) C[(size_t)r * ldc + n0 + 1] = v1;
                }
                if (WH) {
                    uint16_t h0, l0, h1, l1;
                    split1(v0, h0, l0);
                    split1(v1, h1, l1);
                    size_t o = (size_t)r * DDIM + n0;
                    *(uint32_t*)(Chi + o) = (uint32_t)h0 | ((uint32_t)h1 << 16);
                    *(uint32_t*)(Clo + o) = (uint32_t)l0 | ((uint32_t)l1 << 16);
                }
            }
        }
    }
}

// ---------------------------------------------------------------------------
// Launch
// ---------------------------------------------------------------------------
#define SETSM(k) cudaFuncSetAttribute(k, cudaFuncAttributeMaxDynamicSharedMemorySize, SM_TOTAL)

extern "C" void kernel_launch(void* const* d_in, const int* in_sizes, int n_in,
                              void* d_out, int out_size) {
    (void)in_sizes; (void)n_in; (void)out_size;

    const float* mesh    = (const float*)d_in[0];
    const float* grid    = (const float*)d_in[1];
    const float* attrs   = (const float*)d_in[2];
    const int*   esrc    = (const int*)d_in[3];
    const int*   edst    = (const int*)d_in[4];
    const float* emb_w0  = (const float*)d_in[5];
    const float* emb_b0  = (const float*)d_in[6];
    const float* emb_w1  = (const float*)d_in[7];
    const float* emb_b1  = (const float*)d_in[8];
    const float* edge_w0 = (const float*)d_in[9];
    const float* edge_b0 = (const float*)d_in[10];
    const float* edge_w1 = (const float*)d_in[11];
    const float* edge_b1 = (const float*)d_in[12];
    const float* node_w0 = (const float*)d_in[13];
    const float* node_b0 = (const float*)d_in[14];
    const float* node_w1 = (const float*)d_in[15];
    const float* node_b1 = (const float*)d_in[16];
    const float* out_w0  = (const float*)d_in[17];
    const float* out_b0  = (const float*)d_in[18];
    const float* out_w1  = (const float*)d_in[19];
    const float* out_b1  = (const float*)d_in[20];
    float* out = (float*)d_out;

    __nv_bfloat16 *pXhi, *pXlo, *pYhi, *pYlo, *pGhi, *pGlo, *pMhi, *pMlo, *pWThi, *pWTlo;
    float *pE0f, *pAgg, *pUm, *pUg, *pZb;
    cudaGetSymbolAddress((void**)&pXhi, g_xhi);
    cudaGetSymbolAddress((void**)&pXlo, g_xlo);
    cudaGetSymbolAddress((void**)&pYhi, g_yhi);
    cudaGetSymbolAddress((void**)&pYlo, g_ylo);
    cudaGetSymbolAddress((void**)&pGhi, g_ghi);
    cudaGetSymbolAddress((void**)&pGlo, g_glo);
    cudaGetSymbolAddress((void**)&pMhi, g_mhi);
    cudaGetSymbolAddress((void**)&pMlo, g_mlo);
    cudaGetSymbolAddress((void**)&pE0f, g_e0f);
    cudaGetSymbolAddress((void**)&pAgg, g_agg);
    cudaGetSymbolAddress((void**)&pUm, g_um);
    cudaGetSymbolAddress((void**)&pUg, g_ug);
    cudaGetSymbolAddress((void**)&pZb, g_zbias);
    cudaGetSymbolAddress((void**)&pWThi, g_wThi);
    cudaGetSymbolAddress((void**)&pWTlo, g_wTlo);

    SETSM((gemm_mm<false,false,false,false,false,true, true >));
    SETSM((gemm_mm<false,false,false,false,false,true, false>));
    SETSM((gemm_mm<false,true, false,false,true, false,true >));
    SETSM((gemm_mm<false,false,true, true, false,false,false>));
    SETSM((gemm_mm<true, true, false,false,false,false,true >));
    SETSM((gemm_mm<false,false,true, false,false,false,true >));
    SETSM((gemm_mm<false,true, false,false,false,false,true >));

    const int E = NEDGES, G = NGRID;
    dim3 gridE(4, E_PAD / BM);
    dim3 gridG(4, G_PAD / BM);
    dim3 gridM(4, M_PAD / BM);

    // #0: h1 = silu(attrs@emb_w0 + b0) -> X (bf16 hi/lo)
    {
        size_t tot = (size_t)E * 256;
        emb_l1_pack<<<(unsigned)((tot + 255) / 256), 256>>>(attrs, emb_w0, emb_b0, pXhi, pXlo);
    }
    // #1: prep emb_w1
    prep_wT<<<(512 * 512 + 255) / 256, 256>>>(emb_w1, 512, 512, pWThi + OFF_EMBW1, pWTlo + OFF_EMBW1);
    // #2: zero bias
    zero_kernel<<<1, 128>>>((float4*)pZb, DDIM / 4);
    // #3 (ncu capture slot): e0 = h1 @ emb_w1 + b1 -> e0f (fp32) + Y (bf16)
    gemm_mm<false,false,false,false,false,true,true><<<gridE, NTHR, SM_TOTAL>>>(
        pXhi, pXlo, nullptr, nullptr, pWThi + OFF_EMBW1, pWTlo + OFF_EMBW1,
        emb_b1, nullptr, pE0f, DDIM, DDIM, pYhi, pYlo,
        nullptr, nullptr, nullptr, nullptr, nullptr, E, DDIM);
    // #4-#5: split grid / mesh inputs
    split_pack<<<(unsigned)(((size_t)G * 256 + 255) / 256), 256>>>(grid, pGhi, pGlo, (size_t)G * 256);
    split_pack<<<(unsigned)(((size_t)NMESH * 256 + 255) / 256), 256>>>(mesh, pMhi, pMlo, (size_t)NMESH * 256);
    // #6-#8: prep W_e, W_m, W_g
    prep_wT<<<(512 * 512 + 255) / 256, 256>>>(edge_w0 + (size_t)1024 * 512, 512, 512, pWThi + OFF_WE, pWTlo + OFF_WE);
    prep_wT<<<(512 * 512 + 255) / 256, 256>>>(edge_w0, 512, 512, pWThi + OFF_WM, pWTlo + OFF_WM);
    prep_wT<<<(512 * 512 + 255) / 256, 256>>>(edge_w0 + (size_t)512 * 512, 512, 512, pWThi + OFF_WG, pWTlo + OFF_WG);
    // #9: U_m = mesh @ W_m (fp32)
    gemm_mm<false,false,false,false,false,true,false><<<gridM, NTHR, SM_TOTAL>>>(
        pMhi, pMlo, nullptr, nullptr, pWThi + OFF_WM, pWTlo + OFF_WM,
        pZb, nullptr, pUm, DDIM, DDIM, nullptr, nullptr,
        nullptr, nullptr, nullptr, nullptr, nullptr, NMESH, DDIM);
    // #10: U_g = grid @ W_g (fp32)
    gemm_mm<false,false,false,false,false,true,false><<<gridG, NTHR, SM_TOTAL>>>(
        pGhi, pGlo, nullptr, nullptr, pWThi + OFF_WG, pWTlo + OFF_WG,
        pZb, nullptr, pUg, DDIM, DDIM, nullptr, nullptr,
        nullptr, nullptr, nullptr, nullptr, nullptr, G, DDIM);
    // #11: agg = 0
    {
        size_t n4 = (size_t)G * DDIM / 4;
        zero_kernel<<<(unsigned)((n4 + 255) / 256), 256>>>((float4*)pAgg, n4);
    }
    // #12: h = silu(e0@W_e + edge_b0 + Um[src] + Ug[dst]) -> X
    gemm_mm<false,true,false,false,true,false,true><<<gridE, NTHR, SM_TOTAL>>>(
        pYhi, pYlo, nullptr, nullptr, pWThi + OFF_WE, pWTlo + OFF_WE,
        edge_b0, nullptr, nullptr, DDIM, DDIM, pXhi, pXlo,
        pUm, pUg, nullptr, esrc, edst, E, DDIM);
    // #13: prep edge_w1
    prep_wT<<<(512 * 512 + 255) / 256, 256>>>(edge_w1, 512, 512, pWThi + OFF_EDGEW1, pWTlo + OFF_EDGEW1);
    // #14: agg[dst] += e0 + h@edge_w1 + edge_b1
    gemm_mm<false,false,true,true,false,false,false><<<gridE, NTHR, SM_TOTAL>>>(
        pXhi, pXlo, nullptr, nullptr, pWThi + OFF_EDGEW1, pWTlo + OFF_EDGEW1,
        edge_b1, pE0f, nullptr, DDIM, DDIM, nullptr, nullptr,
        nullptr, nullptr, pAgg, nullptr, edst, E, DDIM);
    // #15: split agg -> Y
    split_pack<<<(unsigned)(((size_t)G * 256 + 255) / 256), 256>>>(pAgg, pYhi, pYlo, (size_t)G * 256);
    // #16: prep node_w0 (K=1024)
    prep_wT<<<(512 * 1024 + 255) / 256, 256>>>(node_w0, 1024, 512, pWThi + OFF_NODEW0, pWTlo + OFF_NODEW0);
    // #17: h = silu(concat(grid, agg)@node_w0 + node_b0) -> X
    gemm_mm<true,true,false,false,false,false,true><<<gridG, NTHR, SM_TOTAL>>>(
        pGhi, pGlo, pYhi, pYlo, pWThi + OFF_NODEW0, pWTlo + OFF_NODEW0,
        node_b0, nullptr, nullptr, DDIM, DDIM, pXhi, pXlo,
        nullptr, nullptr, nullptr, nullptr, nullptr, G, 2 * DDIM);
    // #18: prep node_w1
    prep_wT<<<(512 * 512 + 255) / 256, 256>>>(node_w1, 512, 512, pWThi + OFF_NODEW1, pWTlo + OFF_NODEW1);
    // #19: grid_new = grid + h@node_w1 + node_b1 -> Y (bf16)
    gemm_mm<false,false,true,false,false,false,true><<<gridG, NTHR, SM_TOTAL>>>(
        pXhi, pXlo, nullptr, nullptr, pWThi + OFF_NODEW1, pWTlo + OFF_NODEW1,
        node_b1, grid, nullptr, DDIM, DDIM, pYhi, pYlo,
        nullptr, nullptr, nullptr, nullptr, nullptr, G, DDIM);
    // #20: prep out_w0
    prep_wT<<<(512 * 512 + 255) / 256, 256>>>(out_w0, 512, 512, pWThi + OFF_OUTW0, pWTlo + OFF_OUTW0);
    // #21: h = silu(grid_new@out_w0 + out_b0) -> X
    gemm_mm<false,true,false,false,false,false,true><<<gridG, NTHR, SM_TOTAL>>>(
        pYhi, pYlo, nullptr, nullptr, pWThi + OFF_OUTW0, pWTlo + OFF_OUTW0,
        out_b0, nullptr, nullptr, DDIM, DDIM, pXhi, pXlo,
        nullptr, nullptr, nullptr, nullptr, nullptr, G, DDIM);
    // #22: prep out_w1 (padded 471 -> 512)
    prep_wT<<<(512 * 512 + 255) / 256, 256>>>(out_w1, 512, NOUT, pWThi + OFF_OUTW1, pWTlo + OFF_OUTW1);
    // #23: out = h@out_w1 + out_b1 (fp32, N-guard 471)
    gemm_mm<false,false,false,false,false,true,false><<<gridG, NTHR, SM_TOTAL>>>(
        pXhi, pXlo, nullptr, nullptr, pWThi + OFF_OUTW1, pWTlo + OFF_OUTW1,
        out_b1, nullptr, out, NOUT, NOUT, nullptr, nullptr,
        nullptr, nullptr, nullptr, nullptr, nullptr, G, DDIM);
}

// round 16
// speedup vs baseline: 1.6136x; 1.0505x over previous
#include <cuda_runtime.h>
#include <cuda_bf16.h>
#include <math.h>
#include <stdint.h>
#include <stddef.h>

#define NMESH 10242
#define NGRID 65160
#define NEDGES 195480
#define DDIM 512
#define NOUT 471

// padded row counts (multiple of 128 so cp.async tiles stay in-bounds)
#define E_PAD 195584
#define G_PAD 65280
#define M_PAD 10368

// GEMM tiling: CTA 128x128, K-chunk 32 bf16; 8 warps of 64x32; 2 CTAs/SM
#define BM 128
#define BN 128
#define BK 32
#define NTHR 256

#define SMROW 80
// A: 3-deep ring of (hi 10240 | lo 10240); B: 2-deep ring
#define SM_HDR 1024
#define A_BUF 20480
#define B_BASE (SM_HDR + 3 * A_BUF)
#define B_BUF 20480
#define SM_TOTAL (SM_HDR + 3 * A_BUF + 2 * B_BUF)   /* 103424 */

// ---------------------------------------------------------------------------
// Scratch (device globals — no dynamic allocation allowed)
// ---------------------------------------------------------------------------
__device__ __nv_bfloat16 g_xhi[(size_t)E_PAD * DDIM];  // ping
__device__ __nv_bfloat16 g_xlo[(size_t)E_PAD * DDIM];
__device__ __nv_bfloat16 g_yhi[(size_t)E_PAD * DDIM];  // pong
__device__ __nv_bfloat16 g_ylo[(size_t)E_PAD * DDIM];
__device__ __nv_bfloat16 g_ghi[(size_t)G_PAD * DDIM];  // grid pre-split
__device__ __nv_bfloat16 g_glo[(size_t)G_PAD * DDIM];
__device__ __nv_bfloat16 g_mhi[(size_t)M_PAD * DDIM];  // mesh pre-split
__device__ __nv_bfloat16 g_mlo[(size_t)M_PAD * DDIM];
__device__ __nv_bfloat16 g_sbhi[262144];               // small split buffer 512x512
__device__ __nv_bfloat16 g_sblo[262144];
__device__ float g_agg[(size_t)NGRID * DDIM];
__device__ float g_um[(size_t)NMESH * DDIM];
__device__ float g_ug[(size_t)NGRID * DDIM];
__device__ float g_zbias[DDIM];
__device__ float g_bce[DDIM];   // edge_b0 + emb_b1 @ W_e
__device__ float g_bno[DDIM];   // out_b0 + node_b1 @ out_w0
__device__ float g_badd[DDIM];  // emb_b1 + edge_b1

// Pre-transposed / pre-split weights: [N=512 rows][K=512] row-major bf16
#define OFF_EMBW1  0u
#define OFF_WM     262144u
#define OFF_WG     524288u
#define OFF_WE     786432u
#define OFF_EDGEW1 1048576u
#define OFF_N0A    1310720u   /* node_w0 rows 0-511   */
#define OFF_N0B    1572864u   /* node_w0 rows 512-1023 */
#define OFF_OUTW0  1835008u
#define OFF_OUTW1  2097152u   /* padded from 471 cols */
#define OFF_CE     2359296u   /* (emb_w1 @ W_e)^T      */
#define OFF_NO     2621440u   /* (node_w1 @ out_w0)^T  */
#define WT_TOTAL   2883584u
__device__ __nv_bfloat16 g_wThi[WT_TOTAL];
__device__ __nv_bfloat16 g_wTlo[WT_TOTAL];

// ---------------------------------------------------------------------------
// Helpers
// ---------------------------------------------------------------------------
__device__ __forceinline__ uint32_t smem_u32(const void* p) {
    uint32_t a;
    asm("{ .reg .u64 t; cvta.to.shared.u64 t, %1; cvt.u32.u64 %0, t; }"
        : "=r"(a) : "l"(p));
    return a;
}
__device__ __forceinline__ void cpasync16(uint32_t dst, const void* src) {
    asm volatile("cp.async.cg.shared.global [%0], [%1], 16;"
                 :: "r"(dst), "l"(src) : "memory");
}
__device__ __forceinline__ void cp_commit() {
    asm volatile("cp.async.commit_group;" ::: "memory");
}
__device__ __forceinline__ void cp_wait1() {
    asm volatile("cp.async.wait_group 1;" ::: "memory");
}
__device__ __forceinline__ void ldsm4(uint32_t* r, uint32_t addr) {
    asm volatile("ldmatrix.sync.aligned.m8n8.x4.shared.b16 {%0,%1,%2,%3}, [%4];"
                 : "=r"(r[0]), "=r"(r[1]), "=r"(r[2]), "=r"(r[3]) : "r"(addr));
}
__device__ __forceinline__ void mma_bf16(float* c, const uint32_t* a, const uint32_t* b) {
    asm volatile(
        "mma.sync.aligned.m16n8k16.row.col.f32.bf16.bf16.f32 "
        "{%0,%1,%2,%3}, {%4,%5,%6,%7}, {%8,%9}, {%0,%1,%2,%3};"
        : "+f"(c[0]), "+f"(c[1]), "+f"(c[2]), "+f"(c[3])
        : "r"(a[0]), "r"(a[1]), "r"(a[2]), "r"(a[3]), "r"(b[0]), "r"(b[1]));
}
__device__ __forceinline__ void split1(float v, uint16_t& h, uint16_t& l) {
    __nv_bfloat16 hb = __float2bfloat16(v);
    __nv_bfloat16 lb = __float2bfloat16(v - __bfloat162float(hb));
    h = __bfloat16_as_ushort(hb);
    l = __bfloat16_as_ushort(lb);
}
__device__ __forceinline__ float silu_f(float v) {
    return __fdividef(v, 1.0f + __expf(-v));
}

// ---------------------------------------------------------------------------
// Small kernels
// ---------------------------------------------------------------------------
__global__ void emb_l1_pack(const float* __restrict__ attrs,
                            const float* __restrict__ w0,
                            const float* __restrict__ b0,
                            __nv_bfloat16* __restrict__ hi,
                            __nv_bfloat16* __restrict__ lo) {
    size_t idx = (size_t)blockIdx.x * blockDim.x + threadIdx.x;
    if (idx >= (size_t)NEDGES * 256) return;
    int r = (int)(idx >> 8);
    int c2 = (int)(idx & 255) * 2;
    float v0 = b0[c2], v1 = b0[c2 + 1];
#pragma unroll
    for (int j = 0; j < 4; j++) {
        float a = attrs[r * 4 + j];
        v0 = fmaf(a, w0[j * DDIM + c2], v0);
        v1 = fmaf(a, w0[j * DDIM + c2 + 1], v1);
    }
    v0 = silu_f(v0);
    v1 = silu_f(v1);
    uint16_t h0, l0, h1, l1;
    split1(v0, h0, l0);
    split1(v1, h1, l1);
    size_t o = (size_t)r * DDIM + c2;
    *(uint32_t*)(hi + o) = (uint32_t)h0 | ((uint32_t)h1 << 16);
    *(uint32_t*)(lo + o) = (uint32_t)l0 | ((uint32_t)l1 << 16);
}

__global__ void split_pack(const float* __restrict__ src,
                           __nv_bfloat16* __restrict__ hi,
                           __nv_bfloat16* __restrict__ lo, size_t n2) {
    size_t i = (size_t)blockIdx.x * blockDim.x + threadIdx.x;
    if (i >= n2) return;
    float v0 = src[2 * i], v1 = src[2 * i + 1];
    uint16_t h0, l0, h1, l1;
    split1(v0, h0, l0);
    split1(v1, h1, l1);
    *(uint32_t*)(hi + 2 * i) = (uint32_t)h0 | ((uint32_t)h1 << 16);
    *(uint32_t*)(lo + 2 * i) = (uint32_t)l0 | ((uint32_t)l1 << 16);
}

__global__ void zero_kernel(float4* __restrict__ p, size_t n4) {
    size_t i = (size_t)blockIdx.x * blockDim.x + threadIdx.x;
    if (i < n4) p[i] = make_float4(0.f, 0.f, 0.f, 0.f);
}

// W [K, Nsrc] fp32 row-major -> WT hi/lo [512 rows][512] bf16 (rows >= Nsrc zero)
__global__ void prep_wT(const float* __restrict__ W, int Nsrc,
                        __nv_bfloat16* __restrict__ hi,
                        __nv_bfloat16* __restrict__ lo) {
    int idx = blockIdx.x * blockDim.x + threadIdx.x;
    if (idx >= 512 * 512) return;
    int n = idx >> 9;
    int k = idx & 511;
    float v = (n < Nsrc) ? W[(size_t)k * Nsrc + n] : 0.f;
    __nv_bfloat16 h = __float2bfloat16(v);
    hi[idx] = h;
    lo[idx] = __float2bfloat16(v - __bfloat162float(h));
}

// outb[n] = base[n] + sum_j vec[j] * W[j*512 + n]
__global__ void bias_fold(const float* __restrict__ base,
                          const float* __restrict__ vec,
                          const float* __restrict__ W,
                          float* __restrict__ outb) {
    int n = blockIdx.x * blockDim.x + threadIdx.x;
    if (n >= DDIM) return;
    float s = base[n];
    for (int j = 0; j < DDIM; j++) s = fmaf(vec[j], W[(size_t)j * DDIM + n], s);
    outb[n] = s;
}

__global__ void vec_add(const float* __restrict__ a, const float* __restrict__ b,
                        float* __restrict__ o) {
    int n = threadIdx.x + blockIdx.x * blockDim.x;
    if (n < DDIM) o[n] = a[n] + b[n];
}

// ---------------------------------------------------------------------------
// HMMA fused GEMM (128x128 CTA, 8 warps of 64x32, 2 CTAs/SM)
// A pre-split bf16 hi/lo via 3-deep cp.async ring; B 2-deep; wait_group 1.
// All B blocks are [512][512]; CONCAT uses (A2,B2) pair for K in [512,1024).
//   ACT silu | RES += resid fp32 | SCAT atomicAdd agg[dst[r]] |
//   GADD += gUm[src[r]] + gUg[dst[r]] | WF write fp32 C | WH write hi/lo pair
// ---------------------------------------------------------------------------
template <bool CONCAT, bool ACT, bool RES, bool SCAT, bool GADD, bool WF, bool WH>
__global__ void __launch_bounds__(NTHR, 2) gemm_mm(
    const __nv_bfloat16* __restrict__ A1hi, const __nv_bfloat16* __restrict__ A1lo,
    const __nv_bfloat16* __restrict__ A2hi, const __nv_bfloat16* __restrict__ A2lo,
    const __nv_bfloat16* __restrict__ BThi, const __nv_bfloat16* __restrict__ BTlo,
    const __nv_bfloat16* __restrict__ B2hi, const __nv_bfloat16* __restrict__ B2lo,
    const float* __restrict__ bias,
    const float* __restrict__ resid,
    float* __restrict__ C, int ldc, int Nc,
    __nv_bfloat16* __restrict__ Chi, __nv_bfloat16* __restrict__ Clo,
    const float* __restrict__ gUm, const float* __restrict__ gUg,
    float* __restrict__ gagg,
    const int* __restrict__ srcIdx, const int* __restrict__ dstIdx,
    int M, int K) {
    extern __shared__ char sm[];
    const uint32_t smb = smem_u32(sm);
    const int tid = threadIdx.x;
    const int wid = tid >> 5;
    const int lane = tid & 31;
    const int bm = blockIdx.y * BM;
    const int bn = blockIdx.x * BN;
    const int mbase = (wid >> 2) * 64;
    const int nbase = (wid & 3) * 32;

    int* sSrc = (int*)(sm);
    int* sDst = (int*)(sm + 512);
    if (GADD) {
        for (int i = tid; i < BM; i += NTHR) {
            int r = bm + i;
            sSrc[i] = (r < M) ? srcIdx[r] : 0;
            sDst[i] = (r < M) ? dstIdx[r] : 0;
        }
        __syncthreads();
    }

    // ---- cp.async A hi/lo into ring buffer c%3 ----
    auto cpA = [&](int c) {
        int k0 = c * BK;
        uint32_t Ab = smb + SM_HDR + (c % 3) * A_BUF;
#pragma unroll
        for (int it = 0; it < 2; ++it) {
            int idx = it * NTHR + tid;
            int row = idx >> 2;
            int ch = idx & 3;
            int gcol = k0 + ch * 8;
            const __nv_bfloat16 *ph, *pl;
            if (CONCAT && gcol >= 512) {
                size_t o = (size_t)(bm + row) * DDIM + (gcol - 512);
                ph = A2hi + o; pl = A2lo + o;
            } else {
                size_t o = (size_t)(bm + row) * DDIM + gcol;
                ph = A1hi + o; pl = A1lo + o;
            }
            uint32_t doff = (uint32_t)(row * SMROW + ch * 16);
            cpasync16(Ab + doff, ph);
            cpasync16(Ab + 10240 + doff, pl);
        }
    };
    // ---- cp.async B hi/lo into ring buffer c%2 (row stride 512 per half) ----
    auto cpB = [&](int c) {
        int k0 = c * BK;
        uint32_t Bb = smb + B_BASE + (c % 2) * B_BUF;
#pragma unroll
        for (int it = 0; it < 2; ++it) {
            int idx = it * NTHR + tid;
            int row = idx >> 2;
            int ch = idx & 3;
            int gcol = k0 + ch * 8;
            const __nv_bfloat16 *ph, *pl;
            if (CONCAT && gcol >= 512) {
                size_t g = (size_t)(bn + row) * 512 + (gcol - 512);
                ph = B2hi + g; pl = B2lo + g;
            } else {
                size_t g = (size_t)(bn + row) * 512 + gcol;
                ph = BThi + g; pl = BTlo + g;
            }
            uint32_t doff = (uint32_t)(row * SMROW + ch * 16);
            cpasync16(Bb + doff, ph);
            cpasync16(Bb + 10240 + doff, pl);
        }
    };

    float acc[4][4][4];
#pragma unroll
    for (int i = 0; i < 4; i++)
#pragma unroll
        for (int j = 0; j < 4; j++)
#pragma unroll
            for (int e = 0; e < 4; e++) acc[i][j][e] = 0.f;

    const int NC = K / BK;

    // Prologue: group0 = {B0, A0}; group1 = {A1}
    cpB(0);
    cpA(0);
    cp_commit();
    if (1 < NC) cpA(1);
    cp_commit();

    for (int c = 0; c < NC; ++c) {
        cp_wait1();
        __syncthreads();
        if (c + 1 < NC) cpB(c + 1);
        cp_commit();
        if (c + 2 < NC) cpA(c + 2);
        cp_commit();

        const uint32_t Ab = smb + SM_HDR + (c % 3) * A_BUF;
        const uint32_t Bb = smb + B_BASE + (c % 2) * B_BUF;
#pragma unroll
        for (int kh = 0; kh < 2; ++kh) {
            const uint32_t acol = (uint32_t)(kh * 32 + ((lane >> 4) << 4));
            const uint32_t bcol = (uint32_t)(kh * 32 + ((lane >> 3) & 1) * 16);
            const uint32_t brow = (uint32_t)(nbase + ((lane >> 4) << 3) + (lane & 7));
            uint32_t af[4][4], bh[2][4], bl[2][4];
#pragma unroll
            for (int j2 = 0; j2 < 2; ++j2) {
                uint32_t ba = Bb + (brow + j2 * 16) * SMROW + bcol;
                ldsm4(bh[j2], ba);
                ldsm4(bl[j2], ba + 10240);
            }
            // pass 1: A-hi x (B-hi, B-lo)
#pragma unroll
            for (int i = 0; i < 4; ++i)
                ldsm4(af[i], Ab + (uint32_t)((mbase + i * 16 + (lane & 15)) * SMROW) + acol);
#pragma unroll
            for (int i = 0; i < 4; ++i)
#pragma unroll
                for (int j2 = 0; j2 < 2; ++j2) {
                    mma_bf16(acc[i][2 * j2],     af[i], &bh[j2][0]);
                    mma_bf16(acc[i][2 * j2 + 1], af[i], &bh[j2][2]);
                    mma_bf16(acc[i][2 * j2],     af[i], &bl[j2][0]);
                    mma_bf16(acc[i][2 * j2 + 1], af[i], &bl[j2][2]);
                }
            // pass 2: A-lo x B-hi
#pragma unroll
            for (int i = 0; i < 4; ++i)
                ldsm4(af[i], Ab + 10240 + (uint32_t)((mbase + i * 16 + (lane & 15)) * SMROW) + acol);
#pragma unroll
            for (int i = 0; i < 4; ++i)
#pragma unroll
                for (int j2 = 0; j2 < 2; ++j2) {
                    mma_bf16(acc[i][2 * j2],     af[i], &bh[j2][0]);
                    mma_bf16(acc[i][2 * j2 + 1], af[i], &bh[j2][2]);
                }
        }
    }

    // ---- epilogue ----
    const int gid = lane >> 2, tig = lane & 3;
#pragma unroll
    for (int i = 0; i < 4; ++i) {
#pragma unroll
        for (int half = 0; half < 2; ++half) {
            int lr = mbase + i * 16 + gid + half * 8;
            int r = bm + lr;
            if (r >= M) continue;
            int dd = 0;
            if (SCAT) dd = dstIdx[r];
#pragma unroll
            for (int j = 0; j < 4; ++j) {
                int n0 = bn + nbase + j * 8 + tig * 2;
                float v0 = acc[i][j][half * 2];
                float v1 = acc[i][j][half * 2 + 1];
                v0 += bias[n0];
                v1 += (n0 + 1 < Nc) ? bias[n0 + 1] : 0.f;
                if (GADD) {
                    const float* um = gUm + (size_t)sSrc[lr] * DDIM;
                    const float* ug = gUg + (size_t)sDst[lr] * DDIM;
                    v0 += um[n0] + ug[n0];
                    v1 += um[n0 + 1] + ug[n0 + 1];
                }
                if (ACT) { v0 = silu_f(v0); v1 = silu_f(v1); }
                if (RES) {
                    const float* rr = resid + (size_t)r * DDIM;
                    v0 += rr[n0];
                    v1 += rr[n0 + 1];
                }
                if (SCAT) {
                    float* ag = gagg + (size_t)dd * DDIM;
                    atomicAdd(&ag[n0], v0);
                    atomicAdd(&ag[n0 + 1], v1);
                }
                if (WF) {
                    if (n0 < Nc)     C[(size_t)r * ldc + n0] = v0;
                    if (n0 + 1 < Nc) C[(size_t)r * ldc + n0 + 1] = v1;
                }
                if (WH) {
                    uint16_t h0, l0, h1, l1;
                    split1(v0, h0, l0);
                    split1(v1, h1, l1);
                    size_t o = (size_t)r * DDIM + n0;
                    *(uint32_t*)(Chi + o) = (uint32_t)h0 | ((uint32_t)h1 << 16);
                    *(uint32_t*)(Clo + o) = (uint32_t)l0 | ((uint32_t)l1 << 16);
                }
            }
        }
    }
}

// ---------------------------------------------------------------------------
// Launch
// ---------------------------------------------------------------------------
#define SETSM(k) cudaFuncSetAttribute(k, cudaFuncAttributeMaxDynamicSharedMemorySize, SM_TOTAL)

extern "C" void kernel_launch(void* const* d_in, const int* in_sizes, int n_in,
                              void* d_out, int out_size) {
    (void)in_sizes; (void)n_in; (void)out_size;

    const float* mesh    = (const float*)d_in[0];
    const float* grid    = (const float*)d_in[1];
    const float* attrs   = (const float*)d_in[2];
    const int*   esrc    = (const int*)d_in[3];
    const int*   edst    = (const int*)d_in[4];
    const float* emb_w0  = (const float*)d_in[5];
    const float* emb_b0  = (const float*)d_in[6];
    const float* emb_w1  = (const float*)d_in[7];
    const float* emb_b1  = (const float*)d_in[8];
    const float* edge_w0 = (const float*)d_in[9];
    const float* edge_b0 = (const float*)d_in[10];
    const float* edge_w1 = (const float*)d_in[11];
    const float* edge_b1 = (const float*)d_in[12];
    const float* node_w0 = (const float*)d_in[13];
    const float* node_b0 = (const float*)d_in[14];
    const float* node_w1 = (const float*)d_in[15];
    const float* node_b1 = (const float*)d_in[16];
    const float* out_w0  = (const float*)d_in[17];
    const float* out_b0  = (const float*)d_in[18];
    const float* out_w1  = (const float*)d_in[19];
    const float* out_b1  = (const float*)d_in[20];
    float* out = (float*)d_out;

    __nv_bfloat16 *pXhi, *pXlo, *pYhi, *pYlo, *pGhi, *pGlo, *pMhi, *pMlo;
    __nv_bfloat16 *pSBhi, *pSBlo, *pWThi, *pWTlo;
    float *pAgg, *pUm, *pUg, *pZb, *pBce, *pBno, *pBadd;
    cudaGetSymbolAddress((void**)&pXhi, g_xhi);
    cudaGetSymbolAddress((void**)&pXlo, g_xlo);
    cudaGetSymbolAddress((void**)&pYhi, g_yhi);
    cudaGetSymbolAddress((void**)&pYlo, g_ylo);
    cudaGetSymbolAddress((void**)&pGhi, g_ghi);
    cudaGetSymbolAddress((void**)&pGlo, g_glo);
    cudaGetSymbolAddress((void**)&pMhi, g_mhi);
    cudaGetSymbolAddress((void**)&pMlo, g_mlo);
    cudaGetSymbolAddress((void**)&pSBhi, g_sbhi);
    cudaGetSymbolAddress((void**)&pSBlo, g_sblo);
    cudaGetSymbolAddress((void**)&pAgg, g_agg);
    cudaGetSymbolAddress((void**)&pUm, g_um);
    cudaGetSymbolAddress((void**)&pUg, g_ug);
    cudaGetSymbolAddress((void**)&pZb, g_zbias);
    cudaGetSymbolAddress((void**)&pBce, g_bce);
    cudaGetSymbolAddress((void**)&pBno, g_bno);
    cudaGetSymbolAddress((void**)&pBadd, g_badd);
    cudaGetSymbolAddress((void**)&pWThi, g_wThi);
    cudaGetSymbolAddress((void**)&pWTlo, g_wTlo);

    SETSM((gemm_mm<false,false,false,false,false,true, false>)); // fp32 out (Um/Ug/out2)
    SETSM((gemm_mm<false,false,false,false,false,false,true >)); // WH only (W_ce/W_no)
    SETSM((gemm_mm<false,true, false,false,true, false,true >)); // edge h (gather-add)
    SETSM((gemm_mm<true, false,false,true, false,false,false>)); // scatter concat
    SETSM((gemm_mm<true, true, false,false,false,false,true >)); // node1 / out1fold concat
    SETSM((gemm_mm<false,true, false,false,false,false,true >)); // (spare act variant)

    const int E = NEDGES, G = NGRID;
    dim3 gridE(4, E_PAD / BM);
    dim3 gridG(4, G_PAD / BM);
    dim3 gridM(4, M_PAD / BM);
    dim3 grid512(4, 4);

    // #0: h1 = silu(attrs@emb_w0 + b0) -> X
    {
        size_t tot = (size_t)E * 256;
        emb_l1_pack<<<(unsigned)((tot + 255) / 256), 256>>>(attrs, emb_w0, emb_b0, pXhi, pXlo);
    }
    // #1: split grid
    split_pack<<<(unsigned)(((size_t)G * 256 + 255) / 256), 256>>>(grid, pGhi, pGlo, (size_t)G * 256);
    // #2: prep W_g
    prep_wT<<<(512 * 512 + 255) / 256, 256>>>(edge_w0 + (size_t)512 * 512, 512, pWThi + OFF_WG, pWTlo + OFF_WG);
    // #3 (ncu capture slot): U_g = grid @ W_g (fp32)
    gemm_mm<false,false,false,false,false,true,false><<<gridG, NTHR, SM_TOTAL>>>(
        pGhi, pGlo, nullptr, nullptr, pWThi + OFF_WG, pWTlo + OFF_WG, nullptr, nullptr,
        pZb, nullptr, pUg, DDIM, DDIM, nullptr, nullptr,
        nullptr, nullptr, nullptr, nullptr, nullptr, G, DDIM);
    // #4: zero bias vec (note: used by #3; zbias is static-zero at init and never written,
    //     but zero it first call anyway BEFORE #3 would be ideal — keep it before use)
    // (moved up: see ordering note) -- actually ensure zbias zeroed before first use:
    // We zero it at #4 but #3 already read it. To be safe, zero it explicitly first:
    // (zeroing relocated to slot before #3 is not possible without shifting capture;
    //  g_zbias is zero-initialized by CUDA static init, so reads are safe.)
    zero_kernel<<<1, 128>>>((float4*)pZb, DDIM / 4);
    // #5: split mesh
    split_pack<<<(unsigned)(((size_t)NMESH * 256 + 255) / 256), 256>>>(mesh, pMhi, pMlo, (size_t)NMESH * 256);
    // #6: prep W_m
    prep_wT<<<(512 * 512 + 255) / 256, 256>>>(edge_w0, 512, pWThi + OFF_WM, pWTlo + OFF_WM);
    // #7: U_m = mesh @ W_m (fp32)
    gemm_mm<false,false,false,false,false,true,false><<<gridM, NTHR, SM_TOTAL>>>(
        pMhi, pMlo, nullptr, nullptr, pWThi + OFF_WM, pWTlo + OFF_WM, nullptr, nullptr,
        pZb, nullptr, pUm, DDIM, DDIM, nullptr, nullptr,
        nullptr, nullptr, nullptr, nullptr, nullptr, NMESH, DDIM);
    // #8: prep W_e^T  (also A-operand of W_ce GEMM)
    prep_wT<<<(512 * 512 + 255) / 256, 256>>>(edge_w0 + (size_t)1024 * 512, 512, pWThi + OFF_WE, pWTlo + OFF_WE);
    // #9: split emb_w1 -> SB
    split_pack<<<(512 * 256 + 255) / 256, 256>>>(emb_w1, pSBhi, pSBlo, 512 * 256);
    // #10: W_ce^T = (emb_w1 @ W_e)^T : A=W_e^T pair, BT=emb_w1 pair -> CE (WH)
    gemm_mm<false,false,false,false,false,false,true><<<grid512, NTHR, SM_TOTAL>>>(
        pWThi + OFF_WE, pWTlo + OFF_WE, nullptr, nullptr, pSBhi, pSBlo, nullptr, nullptr,
        pZb, nullptr, nullptr, DDIM, DDIM, pWThi + OFF_CE, pWTlo + OFF_CE,
        nullptr, nullptr, nullptr, nullptr, nullptr, 512, DDIM);
    // #11: b_ce = edge_b0 + emb_b1 @ W_e
    bias_fold<<<2, 256>>>(edge_b0, emb_b1, edge_w0 + (size_t)1024 * 512, pBce);
    // #12-#13: prep emb_w1^T, edge_w1^T (scatter concat B halves)
    prep_wT<<<(512 * 512 + 255) / 256, 256>>>(emb_w1, 512, pWThi + OFF_EMBW1, pWTlo + OFF_EMBW1);
    prep_wT<<<(512 * 512 + 255) / 256, 256>>>(edge_w1, 512, pWThi + OFF_EDGEW1, pWTlo + OFF_EDGEW1);
    // #14: badd = emb_b1 + edge_b1
    vec_add<<<2, 256>>>(emb_b1, edge_b1, pBadd);
    // #15: agg = 0
    {
        size_t n4 = (size_t)G * DDIM / 4;
        zero_kernel<<<(unsigned)((n4 + 255) / 256), 256>>>((float4*)pAgg, n4);
    }
    // #16: h = silu(h1 @ W_ce + b_ce + Um[src] + Ug[dst]) -> Y   (E, K=512)
    gemm_mm<false,true,false,false,true,false,true><<<gridE, NTHR, SM_TOTAL>>>(
        pXhi, pXlo, nullptr, nullptr, pWThi + OFF_CE, pWTlo + OFF_CE, nullptr, nullptr,
        pBce, nullptr, nullptr, DDIM, DDIM, pYhi, pYlo,
        pUm, pUg, nullptr, esrc, edst, E, DDIM);
    // #17: agg[dst] += concat(h1, h) @ [emb_w1; edge_w1] + badd   (E, K=1024)
    gemm_mm<true,false,false,true,false,false,false><<<gridE, NTHR, SM_TOTAL>>>(
        pXhi, pXlo, pYhi, pYlo,
        pWThi + OFF_EMBW1, pWTlo + OFF_EMBW1, pWThi + OFF_EDGEW1, pWTlo + OFF_EDGEW1,
        pBadd, nullptr, nullptr, DDIM, DDIM, nullptr, nullptr,
        nullptr, nullptr, pAgg, nullptr, edst, E, 2 * DDIM);
    // #18: split agg -> Y
    split_pack<<<(unsigned)(((size_t)G * 256 + 255) / 256), 256>>>(pAgg, pYhi, pYlo, (size_t)G * 256);
    // #19-#20: prep node_w0 halves
    prep_wT<<<(512 * 512 + 255) / 256, 256>>>(node_w0, 512, pWThi + OFF_N0A, pWTlo + OFF_N0A);
    prep_wT<<<(512 * 512 + 255) / 256, 256>>>(node_w0 + (size_t)512 * 512, 512, pWThi + OFF_N0B, pWTlo + OFF_N0B);
    // #21: h2 = silu(concat(grid, agg) @ node_w0 + node_b0) -> X   (G, K=1024)
    gemm_mm<true,true,false,false,false,false,true><<<gridG, NTHR, SM_TOTAL>>>(
        pGhi, pGlo, pYhi, pYlo,
        pWThi + OFF_N0A, pWTlo + OFF_N0A, pWThi + OFF_N0B, pWTlo + OFF_N0B,
        node_b0, nullptr, nullptr, DDIM, DDIM, pXhi, pXlo,
        nullptr, nullptr, nullptr, nullptr, nullptr, G, 2 * DDIM);
    // #22: prep out_w0^T
    prep_wT<<<(512 * 512 + 255) / 256, 256>>>(out_w0, 512, pWThi + OFF_OUTW0, pWTlo + OFF_OUTW0);
    // #23: split node_w1 -> SB
    split_pack<<<(512 * 256 + 255) / 256, 256>>>(node_w1, pSBhi, pSBlo, 512 * 256);
    // #24: W_no^T = (node_w1 @ out_w0)^T : A=out_w0^T, BT=node_w1 pair -> NO (WH)
    gemm_mm<false,false,false,false,false,false,true><<<grid512, NTHR, SM_TOTAL>>>(
        pWThi + OFF_OUTW0, pWTlo + OFF_OUTW0, nullptr, nullptr, pSBhi, pSBlo, nullptr, nullptr,
        pZb, nullptr, nullptr, DDIM, DDIM, pWThi + OFF_NO, pWTlo + OFF_NO,
        nullptr, nullptr, nullptr, nullptr, nullptr, 512, DDIM);
    // #25: b_no = out_b0 + node_b1 @ out_w0
    bias_fold<<<2, 256>>>(out_b0, node_b1, out_w0, pBno);
    // #26: o1 = silu(concat(grid, h2) @ [out_w0; W_no] + b_no) -> Y   (G, K=1024)
    gemm_mm<true,true,false,false,false,false,true><<<gridG, NTHR, SM_TOTAL>>>(
        pGhi, pGlo, pXhi, pXlo,
        pWThi + OFF_OUTW0, pWTlo + OFF_OUTW0, pWThi + OFF_NO, pWTlo + OFF_NO,
        pBno, nullptr, nullptr, DDIM, DDIM, pYhi, pYlo,
        nullptr, nullptr, nullptr, nullptr, nullptr, G, 2 * DDIM);
    // #27: prep out_w1 (padded 471 -> 512)
    prep_wT<<<(512 * 512 + 255) / 256, 256>>>(out_w1, NOUT, pWThi + OFF_OUTW1, pWTlo + OFF_OUTW1);
    // #28: out = o1 @ out_w1 + out_b1 (fp32, N-guard 471)
    gemm_mm<false,false,false,false,false,true,false><<<gridG, NTHR, SM_TOTAL>>>(
        pYhi, pYlo, nullptr, nullptr, pWThi + OFF_OUTW1, pWTlo + OFF_OUTW1, nullptr, nullptr,
        out_b1, nullptr, out, NOUT, NOUT, nullptr, nullptr,
        nullptr, nullptr, nullptr, nullptr, nullptr, G, DDIM);
}

// round 17
// speedup vs baseline: 1.9907x; 1.2337x over previous
#include <cuda_runtime.h>
#include <cuda_bf16.h>
#include <math.h>
#include <stdint.h>
#include <stddef.h>

#define NMESH 10242
#define NGRID 65160
#define NEDGES 195480
#define DDIM 512
#define NOUT 471

#define E_PAD 195584
#define G_PAD 65280
#define M_PAD 10368

#define BM 128
#define BN 128
#define BK 32
#define NTHR 256

#define SMROW 80
#define SM_HDR 1024
#define A_BUF 20480
#define B_BASE (SM_HDR + 3 * A_BUF)
#define B_BUF 20480
#define SM_TOTAL (SM_HDR + 3 * A_BUF + 2 * B_BUF)   /* 103424 */

// ---------------------------------------------------------------------------
// Scratch (device globals — no dynamic allocation allowed)
// ---------------------------------------------------------------------------
__device__ __nv_bfloat16 g_xhi[(size_t)E_PAD * DDIM];
__device__ __nv_bfloat16 g_xlo[(size_t)E_PAD * DDIM];
__device__ __nv_bfloat16 g_yhi[(size_t)E_PAD * DDIM];
__device__ __nv_bfloat16 g_ylo[(size_t)E_PAD * DDIM];
__device__ __nv_bfloat16 g_zhi[(size_t)G_PAD * DDIM];  // agg pair
__device__ __nv_bfloat16 g_zlo[(size_t)G_PAD * DDIM];
__device__ __nv_bfloat16 g_ghi[(size_t)G_PAD * DDIM];
__device__ __nv_bfloat16 g_glo[(size_t)G_PAD * DDIM];
__device__ __nv_bfloat16 g_mhi[(size_t)M_PAD * DDIM];
__device__ __nv_bfloat16 g_mlo[(size_t)M_PAD * DDIM];
__device__ __nv_bfloat16 g_sbhi[262144];
__device__ __nv_bfloat16 g_sblo[262144];
__device__ float g_sh1[(size_t)NGRID * DDIM];  // segsum(h1)
__device__ float g_sh[(size_t)NGRID * DDIM];   // segsum(h)
__device__ float g_cnt[NGRID];                 // edge count per grid node
__device__ float g_um[(size_t)NMESH * DDIM];
__device__ float g_ug[(size_t)NGRID * DDIM];
__device__ float g_zbias[DDIM];
__device__ float g_bce[DDIM];
__device__ float g_bno[DDIM];
__device__ float g_badd[DDIM];

// Pre-transposed / pre-split weights: [N=512 rows][K=512] bf16
#define OFF_EMBW1  0u
#define OFF_WM     262144u
#define OFF_WG     524288u
#define OFF_WE     786432u
#define OFF_EDGEW1 1048576u
#define OFF_N0A    1310720u
#define OFF_N0B    1572864u
#define OFF_OUTW0  1835008u
#define OFF_OUTW1  2097152u
#define OFF_CE     2359296u
#define OFF_NO     2621440u
#define WT_TOTAL   2883584u
__device__ __nv_bfloat16 g_wThi[WT_TOTAL];
__device__ __nv_bfloat16 g_wTlo[WT_TOTAL];

// ---------------------------------------------------------------------------
// Helpers
// ---------------------------------------------------------------------------
__device__ __forceinline__ uint32_t smem_u32(const void* p) {
    uint32_t a;
    asm("{ .reg .u64 t; cvta.to.shared.u64 t, %1; cvt.u32.u64 %0, t; }"
        : "=r"(a) : "l"(p));
    return a;
}
__device__ __forceinline__ void cpasync16(uint32_t dst, const void* src) {
    asm volatile("cp.async.cg.shared.global [%0], [%1], 16;"
                 :: "r"(dst), "l"(src) : "memory");
}
__device__ __forceinline__ void cp_commit() {
    asm volatile("cp.async.commit_group;" ::: "memory");
}
__device__ __forceinline__ void cp_wait1() {
    asm volatile("cp.async.wait_group 1;" ::: "memory");
}
__device__ __forceinline__ void ldsm4(uint32_t* r, uint32_t addr) {
    asm volatile("ldmatrix.sync.aligned.m8n8.x4.shared.b16 {%0,%1,%2,%3}, [%4];"
                 : "=r"(r[0]), "=r"(r[1]), "=r"(r[2]), "=r"(r[3]) : "r"(addr));
}
__device__ __forceinline__ void mma_bf16(float* c, const uint32_t* a, const uint32_t* b) {
    asm volatile(
        "mma.sync.aligned.m16n8k16.row.col.f32.bf16.bf16.f32 "
        "{%0,%1,%2,%3}, {%4,%5,%6,%7}, {%8,%9}, {%0,%1,%2,%3};"
        : "+f"(c[0]), "+f"(c[1]), "+f"(c[2]), "+f"(c[3])
        : "r"(a[0]), "r"(a[1]), "r"(a[2]), "r"(a[3]), "r"(b[0]), "r"(b[1]));
}
__device__ __forceinline__ void split1(float v, uint16_t& h, uint16_t& l) {
    __nv_bfloat16 hb = __float2bfloat16(v);
    __nv_bfloat16 lb = __float2bfloat16(v - __bfloat162float(hb));
    h = __bfloat16_as_ushort(hb);
    l = __bfloat16_as_ushort(lb);
}
__device__ __forceinline__ float silu_f(float v) {
    return __fdividef(v, 1.0f + __expf(-v));
}

// ---------------------------------------------------------------------------
// Small kernels
// ---------------------------------------------------------------------------
// h1 = silu(attrs@emb_w0+b0) -> pair X; also atomically scatter into sh1[dst]
__global__ void emb_l1_pack(const float* __restrict__ attrs,
                            const float* __restrict__ w0,
                            const float* __restrict__ b0,
                            const int* __restrict__ edst,
                            __nv_bfloat16* __restrict__ hi,
                            __nv_bfloat16* __restrict__ lo,
                            float* __restrict__ sh1) {
    size_t idx = (size_t)blockIdx.x * blockDim.x + threadIdx.x;
    if (idx >= (size_t)NEDGES * 256) return;
    int r = (int)(idx >> 8);
    int c2 = (int)(idx & 255) * 2;
    float v0 = b0[c2], v1 = b0[c2 + 1];
#pragma unroll
    for (int j = 0; j < 4; j++) {
        float a = attrs[r * 4 + j];
        v0 = fmaf(a, w0[j * DDIM + c2], v0);
        v1 = fmaf(a, w0[j * DDIM + c2 + 1], v1);
    }
    v0 = silu_f(v0);
    v1 = silu_f(v1);
    int d = edst[r];
    atomicAdd(&sh1[(size_t)d * DDIM + c2], v0);
    atomicAdd(&sh1[(size_t)d * DDIM + c2 + 1], v1);
    uint16_t h0, l0, h1, l1;
    split1(v0, h0, l0);
    split1(v1, h1, l1);
    size_t o = (size_t)r * DDIM + c2;
    *(uint32_t*)(hi + o) = (uint32_t)h0 | ((uint32_t)h1 << 16);
    *(uint32_t*)(lo + o) = (uint32_t)l0 | ((uint32_t)l1 << 16);
}

__global__ void cnt_kernel(const int* __restrict__ edst, float* __restrict__ cnt) {
    int i = blockIdx.x * blockDim.x + threadIdx.x;
    if (i < NEDGES) atomicAdd(&cnt[edst[i]], 1.0f);
}

__global__ void split_pack(const float* __restrict__ src,
                           __nv_bfloat16* __restrict__ hi,
                           __nv_bfloat16* __restrict__ lo, size_t n2) {
    size_t i = (size_t)blockIdx.x * blockDim.x + threadIdx.x;
    if (i >= n2) return;
    float v0 = src[2 * i], v1 = src[2 * i + 1];
    uint16_t h0, l0, h1, l1;
    split1(v0, h0, l0);
    split1(v1, h1, l1);
    *(uint32_t*)(hi + 2 * i) = (uint32_t)h0 | ((uint32_t)h1 << 16);
    *(uint32_t*)(lo + 2 * i) = (uint32_t)l0 | ((uint32_t)l1 << 16);
}

__global__ void zero_kernel(float4* __restrict__ p, size_t n4) {
    size_t i = (size_t)blockIdx.x * blockDim.x + threadIdx.x;
    if (i < n4) p[i] = make_float4(0.f, 0.f, 0.f, 0.f);
}

__global__ void prep_wT(const float* __restrict__ W, int Nsrc,
                        __nv_bfloat16* __restrict__ hi,
                        __nv_bfloat16* __restrict__ lo) {
    int idx = blockIdx.x * blockDim.x + threadIdx.x;
    if (idx >= 512 * 512) return;
    int n = idx >> 9;
    int k = idx & 511;
    float v = (n < Nsrc) ? W[(size_t)k * Nsrc + n] : 0.f;
    __nv_bfloat16 h = __float2bfloat16(v);
    hi[idx] = h;
    lo[idx] = __float2bfloat16(v - __bfloat162float(h));
}

__global__ void bias_fold(const float* __restrict__ base,
                          const float* __restrict__ vec,
                          const float* __restrict__ W,
                          float* __restrict__ outb) {
    int n = blockIdx.x * blockDim.x + threadIdx.x;
    if (n >= DDIM) return;
    float s = base[n];
    for (int j = 0; j < DDIM; j++) s = fmaf(vec[j], W[(size_t)j * DDIM + n], s);
    outb[n] = s;
}

__global__ void vec_add(const float* __restrict__ a, const float* __restrict__ b,
                        float* __restrict__ o) {
    int n = threadIdx.x + blockIdx.x * blockDim.x;
    if (n < DDIM) o[n] = a[n] + b[n];
}

// ---------------------------------------------------------------------------
// HMMA fused GEMM (128x128 CTA, 8 warps of 64x32, 2 CTAs/SM)
// A pre-split bf16 hi/lo via 3-deep cp.async ring; B 2-deep; wait_group 1.
// All B blocks [512][512]; CONCAT uses (A2,B2) for K in [512,1024).
//   ACT silu | SCAT atomicAdd gagg[dst[r]] | GADD += gUm[src[r]] + gUg[dst[r]]
//   WF fp32 C | WH hi/lo pair | CB += gcnt[r]*cbv[n]
// ---------------------------------------------------------------------------
template <bool CONCAT, bool ACT, bool SCAT, bool GADD, bool WF, bool WH, bool CB>
__global__ void __launch_bounds__(NTHR, 2) gemm_mm(
    const __nv_bfloat16* __restrict__ A1hi, const __nv_bfloat16* __restrict__ A1lo,
    const __nv_bfloat16* __restrict__ A2hi, const __nv_bfloat16* __restrict__ A2lo,
    const __nv_bfloat16* __restrict__ BThi, const __nv_bfloat16* __restrict__ BTlo,
    const __nv_bfloat16* __restrict__ B2hi, const __nv_bfloat16* __restrict__ B2lo,
    const float* __restrict__ bias,
    float* __restrict__ C, int ldc, int Nc,
    __nv_bfloat16* __restrict__ Chi, __nv_bfloat16* __restrict__ Clo,
    const float* __restrict__ gUm, const float* __restrict__ gUg,
    float* __restrict__ gagg,
    const float* __restrict__ gcnt, const float* __restrict__ cbv,
    const int* __restrict__ srcIdx, const int* __restrict__ dstIdx,
    int M, int K) {
    extern __shared__ char sm[];
    const uint32_t smb = smem_u32(sm);
    const int tid = threadIdx.x;
    const int wid = tid >> 5;
    const int lane = tid & 31;
    const int bm = blockIdx.y * BM;
    const int bn = blockIdx.x * BN;
    const int mbase = (wid >> 2) * 64;
    const int nbase = (wid & 3) * 32;

    int* sSrc = (int*)(sm);
    int* sDst = (int*)(sm + 512);
    if (GADD) {
        for (int i = tid; i < BM; i += NTHR) {
            int r = bm + i;
            sSrc[i] = (r < M) ? srcIdx[r] : 0;
            sDst[i] = (r < M) ? dstIdx[r] : 0;
        }
        __syncthreads();
    }

    auto cpA = [&](int c) {
        int k0 = c * BK;
        uint32_t Ab = smb + SM_HDR + (c % 3) * A_BUF;
#pragma unroll
        for (int it = 0; it < 2; ++it) {
            int idx = it * NTHR + tid;
            int row = idx >> 2;
            int ch = idx & 3;
            int gcol = k0 + ch * 8;
            const __nv_bfloat16 *ph, *pl;
            if (CONCAT && gcol >= 512) {
                size_t o = (size_t)(bm + row) * DDIM + (gcol - 512);
                ph = A2hi + o; pl = A2lo + o;
            } else {
                size_t o = (size_t)(bm + row) * DDIM + gcol;
                ph = A1hi + o; pl = A1lo + o;
            }
            uint32_t doff = (uint32_t)(row * SMROW + ch * 16);
            cpasync16(Ab + doff, ph);
            cpasync16(Ab + 10240 + doff, pl);
        }
    };
    auto cpB = [&](int c) {
        int k0 = c * BK;
        uint32_t Bb = smb + B_BASE + (c % 2) * B_BUF;
#pragma unroll
        for (int it = 0; it < 2; ++it) {
            int idx = it * NTHR + tid;
            int row = idx >> 2;
            int ch = idx & 3;
            int gcol = k0 + ch * 8;
            const __nv_bfloat16 *ph, *pl;
            if (CONCAT && gcol >= 512) {
                size_t g = (size_t)(bn + row) * 512 + (gcol - 512);
                ph = B2hi + g; pl = B2lo + g;
            } else {
                size_t g = (size_t)(bn + row) * 512 + gcol;
                ph = BThi + g; pl = BTlo + g;
            }
            uint32_t doff = (uint32_t)(row * SMROW + ch * 16);
            cpasync16(Bb + doff, ph);
            cpasync16(Bb + 10240 + doff, pl);
        }
    };

    float acc[4][4][4];
#pragma unroll
    for (int i = 0; i < 4; i++)
#pragma unroll
        for (int j = 0; j < 4; j++)
#pragma unroll
            for (int e = 0; e < 4; e++) acc[i][j][e] = 0.f;

    const int NC = K / BK;

    cpB(0);
    cpA(0);
    cp_commit();
    if (1 < NC) cpA(1);
    cp_commit();

    for (int c = 0; c < NC; ++c) {
        cp_wait1();
        __syncthreads();
        if (c + 1 < NC) cpB(c + 1);
        cp_commit();
        if (c + 2 < NC) cpA(c + 2);
        cp_commit();

        const uint32_t Ab = smb + SM_HDR + (c % 3) * A_BUF;
        const uint32_t Bb = smb + B_BASE + (c % 2) * B_BUF;
#pragma unroll
        for (int kh = 0; kh < 2; ++kh) {
            const uint32_t acol = (uint32_t)(kh * 32 + ((lane >> 4) << 4));
            const uint32_t bcol = (uint32_t)(kh * 32 + ((lane >> 3) & 1) * 16);
            const uint32_t brow = (uint32_t)(nbase + ((lane >> 4) << 3) + (lane & 7));
            uint32_t af[4][4], bh[2][4], bl[2][4];
#pragma unroll
            for (int j2 = 0; j2 < 2; ++j2) {
                uint32_t ba = Bb + (brow + j2 * 16) * SMROW + bcol;
                ldsm4(bh[j2], ba);
                ldsm4(bl[j2], ba + 10240);
            }
#pragma unroll
            for (int i = 0; i < 4; ++i)
                ldsm4(af[i], Ab + (uint32_t)((mbase + i * 16 + (lane & 15)) * SMROW) + acol);
#pragma unroll
            for (int i = 0; i < 4; ++i)
#pragma unroll
                for (int j2 = 0; j2 < 2; ++j2) {
                    mma_bf16(acc[i][2 * j2],     af[i], &bh[j2][0]);
                    mma_bf16(acc[i][2 * j2 + 1], af[i], &bh[j2][2]);
                    mma_bf16(acc[i][2 * j2],     af[i], &bl[j2][0]);
                    mma_bf16(acc[i][2 * j2 + 1], af[i], &bl[j2][2]);
                }
#pragma unroll
            for (int i = 0; i < 4; ++i)
                ldsm4(af[i], Ab + 10240 + (uint32_t)((mbase + i * 16 + (lane & 15)) * SMROW) + acol);
#pragma unroll
            for (int i = 0; i < 4; ++i)
#pragma unroll
                for (int j2 = 0; j2 < 2; ++j2) {
                    mma_bf16(acc[i][2 * j2],     af[i], &bh[j2][0]);
                    mma_bf16(acc[i][2 * j2 + 1], af[i], &bh[j2][2]);
                }
        }
    }

    // ---- epilogue ----
    const int gid = lane >> 2, tig = lane & 3;
#pragma unroll
    for (int i = 0; i < 4; ++i) {
#pragma unroll
        for (int half = 0; half < 2; ++half) {
            int lr = mbase + i * 16 + gid + half * 8;
            int r = bm + lr;
            if (r >= M) continue;
            int dd = 0;
            if (SCAT) dd = dstIdx[r];
            float cv = 0.f;
            if (CB) cv = gcnt[r];
#pragma unroll
            for (int j = 0; j < 4; ++j) {
                int n0 = bn + nbase + j * 8 + tig * 2;
                float v0 = acc[i][j][half * 2];
                float v1 = acc[i][j][half * 2 + 1];
                v0 += bias[n0];
                v1 += (n0 + 1 < Nc) ? bias[n0 + 1] : 0.f;
                if (CB) {
                    v0 += cv * cbv[n0];
                    v1 += cv * cbv[n0 + 1];
                }
                if (GADD) {
                    const float* um = gUm + (size_t)sSrc[lr] * DDIM;
                    const float* ug = gUg + (size_t)sDst[lr] * DDIM;
                    v0 += um[n0] + ug[n0];
                    v1 += um[n0 + 1] + ug[n0 + 1];
                }
                if (ACT) { v0 = silu_f(v0); v1 = silu_f(v1); }
                if (SCAT) {
                    float* ag = gagg + (size_t)dd * DDIM;
                    atomicAdd(&ag[n0], v0);
                    atomicAdd(&ag[n0 + 1], v1);
                }
                if (WF) {
                    if (n0 < Nc)     C[(size_t)r * ldc + n0] = v0;
                    if (n0 + 1 < Nc) C[(size_t)r * ldc + n0 + 1] = v1;
                }
                if (WH) {
                    uint16_t h0, l0, h1, l1;
                    split1(v0, h0, l0);
                    split1(v1, h1, l1);
                    size_t o = (size_t)r * DDIM + n0;
                    *(uint32_t*)(Chi + o) = (uint32_t)h0 | ((uint32_t)h1 << 16);
                    *(uint32_t*)(Clo + o) = (uint32_t)l0 | ((uint32_t)l1 << 16);
                }
            }
        }
    }
}

// ---------------------------------------------------------------------------
// Launch
// ---------------------------------------------------------------------------
#define SETSM(k) cudaFuncSetAttribute(k, cudaFuncAttributeMaxDynamicSharedMemorySize, SM_TOTAL)

extern "C" void kernel_launch(void* const* d_in, const int* in_sizes, int n_in,
                              void* d_out, int out_size) {
    (void)in_sizes; (void)n_in; (void)out_size;

    const float* mesh    = (const float*)d_in[0];
    const float* grid    = (const float*)d_in[1];
    const float* attrs   = (const float*)d_in[2];
    const int*   esrc    = (const int*)d_in[3];
    const int*   edst    = (const int*)d_in[4];
    const float* emb_w0  = (const float*)d_in[5];
    const float* emb_b0  = (const float*)d_in[6];
    const float* emb_w1  = (const float*)d_in[7];
    const float* emb_b1  = (const float*)d_in[8];
    const float* edge_w0 = (const float*)d_in[9];
    const float* edge_b0 = (const float*)d_in[10];
    const float* edge_w1 = (const float*)d_in[11];
    const float* edge_b1 = (const float*)d_in[12];
    const float* node_w0 = (const float*)d_in[13];
    const float* node_b0 = (const float*)d_in[14];
    const float* node_w1 = (const float*)d_in[15];
    const float* node_b1 = (const float*)d_in[16];
    const float* out_w0  = (const float*)d_in[17];
    const float* out_b0  = (const float*)d_in[18];
    const float* out_w1  = (const float*)d_in[19];
    const float* out_b1  = (const float*)d_in[20];
    float* out = (float*)d_out;

    __nv_bfloat16 *pXhi, *pXlo, *pYhi, *pYlo, *pZhi, *pZlo, *pGhi, *pGlo, *pMhi, *pMlo;
    __nv_bfloat16 *pSBhi, *pSBlo, *pWThi, *pWTlo;
    float *pSh1, *pSh, *pCnt, *pUm, *pUg, *pZb, *pBce, *pBno, *pBadd;
    cudaGetSymbolAddress((void**)&pXhi, g_xhi);
    cudaGetSymbolAddress((void**)&pXlo, g_xlo);
    cudaGetSymbolAddress((void**)&pYhi, g_yhi);
    cudaGetSymbolAddress((void**)&pYlo, g_ylo);
    cudaGetSymbolAddress((void**)&pZhi, g_zhi);
    cudaGetSymbolAddress((void**)&pZlo, g_zlo);
    cudaGetSymbolAddress((void**)&pGhi, g_ghi);
    cudaGetSymbolAddress((void**)&pGlo, g_glo);
    cudaGetSymbolAddress((void**)&pMhi, g_mhi);
    cudaGetSymbolAddress((void**)&pMlo, g_mlo);
    cudaGetSymbolAddress((void**)&pSBhi, g_sbhi);
    cudaGetSymbolAddress((void**)&pSBlo, g_sblo);
    cudaGetSymbolAddress((void**)&pSh1, g_sh1);
    cudaGetSymbolAddress((void**)&pSh, g_sh);
    cudaGetSymbolAddress((void**)&pCnt, g_cnt);
    cudaGetSymbolAddress((void**)&pUm, g_um);
    cudaGetSymbolAddress((void**)&pUg, g_ug);
    cudaGetSymbolAddress((void**)&pZb, g_zbias);
    cudaGetSymbolAddress((void**)&pBce, g_bce);
    cudaGetSymbolAddress((void**)&pBno, g_bno);
    cudaGetSymbolAddress((void**)&pBadd, g_badd);
    cudaGetSymbolAddress((void**)&pWThi, g_wThi);
    cudaGetSymbolAddress((void**)&pWTlo, g_wTlo);

    // <CONCAT,ACT,SCAT,GADD,WF,WH,CB>
    SETSM((gemm_mm<false,false,false,false,true, false,false>)); // fp32 out: Ug/Um/out2
    SETSM((gemm_mm<false,false,false,false,false,true, false>)); // WH only: W_ce/W_no
    SETSM((gemm_mm<false,true, true, true, false,false,false>)); // edge-h: ACT+GADD+SCAT
    SETSM((gemm_mm<true, false,false,false,false,true, true >)); // agg: CONCAT+CB+WH
    SETSM((gemm_mm<true, true, false,false,false,true, false>)); // node1/out1: CONCAT+ACT+WH

    const int E = NEDGES, G = NGRID;
    dim3 gridE(4, E_PAD / BM);
    dim3 gridG(4, G_PAD / BM);
    dim3 gridM(4, M_PAD / BM);
    dim3 grid512(4, 4);

    // #0: split grid
    split_pack<<<(unsigned)(((size_t)G * 256 + 255) / 256), 256>>>(grid, pGhi, pGlo, (size_t)G * 256);
    // #1: prep W_g
    prep_wT<<<(512 * 512 + 255) / 256, 256>>>(edge_w0 + (size_t)512 * 512, 512, pWThi + OFF_WG, pWTlo + OFF_WG);
    // #2: zero zbias
    zero_kernel<<<1, 128>>>((float4*)pZb, DDIM / 4);
    // #3 (ncu capture slot): U_g = grid @ W_g (fp32)
    gemm_mm<false,false,false,false,true,false,false><<<gridG, NTHR, SM_TOTAL>>>(
        pGhi, pGlo, nullptr, nullptr, pWThi + OFF_WG, pWTlo + OFF_WG, nullptr, nullptr,
        pZb, pUg, DDIM, DDIM, nullptr, nullptr,
        nullptr, nullptr, nullptr, nullptr, nullptr, nullptr, nullptr, G, DDIM);
    // #4-#6: zero S_h1, S_h, cnt
    {
        size_t n4 = (size_t)G * DDIM / 4;
        zero_kernel<<<(unsigned)((n4 + 255) / 256), 256>>>((float4*)pSh1, n4);
        zero_kernel<<<(unsigned)((n4 + 255) / 256), 256>>>((float4*)pSh, n4);
        zero_kernel<<<(G / 4 + 255) / 256, 256>>>((float4*)pCnt, G / 4);
    }
    // #7: h1 = silu(attrs@emb_w0+b0) -> X, scatter into S_h1[dst]
    {
        size_t tot = (size_t)E * 256;
        emb_l1_pack<<<(unsigned)((tot + 255) / 256), 256>>>(attrs, emb_w0, emb_b0, edst, pXhi, pXlo, pSh1);
    }
    // #8: cnt histogram
    cnt_kernel<<<(E + 255) / 256, 256>>>(edst, pCnt);
    // #9: split mesh
    split_pack<<<(unsigned)(((size_t)NMESH * 256 + 255) / 256), 256>>>(mesh, pMhi, pMlo, (size_t)NMESH * 256);
    // #10: prep W_m
    prep_wT<<<(512 * 512 + 255) / 256, 256>>>(edge_w0, 512, pWThi + OFF_WM, pWTlo + OFF_WM);
    // #11: U_m = mesh @ W_m (fp32)
    gemm_mm<false,false,false,false,true,false,false><<<gridM, NTHR, SM_TOTAL>>>(
        pMhi, pMlo, nullptr, nullptr, pWThi + OFF_WM, pWTlo + OFF_WM, nullptr, nullptr,
        pZb, pUm, DDIM, DDIM, nullptr, nullptr,
        nullptr, nullptr, nullptr, nullptr, nullptr, nullptr, nullptr, NMESH, DDIM);
    // #12: prep W_e^T
    prep_wT<<<(512 * 512 + 255) / 256, 256>>>(edge_w0 + (size_t)1024 * 512, 512, pWThi + OFF_WE, pWTlo + OFF_WE);
    // #13: split emb_w1 -> SB
    split_pack<<<(512 * 256 + 255) / 256, 256>>>(emb_w1, pSBhi, pSBlo, 512 * 256);
    // #14: W_ce^T = (emb_w1 @ W_e)^T
    gemm_mm<false,false,false,false,false,true,false><<<grid512, NTHR, SM_TOTAL>>>(
        pWThi + OFF_WE, pWTlo + OFF_WE, nullptr, nullptr, pSBhi, pSBlo, nullptr, nullptr,
        pZb, nullptr, DDIM, DDIM, pWThi + OFF_CE, pWTlo + OFF_CE,
        nullptr, nullptr, nullptr, nullptr, nullptr, nullptr, nullptr, 512, DDIM);
    // #15: b_ce = edge_b0 + emb_b1 @ W_e
    bias_fold<<<2, 256>>>(edge_b0, emb_b1, edge_w0 + (size_t)1024 * 512, pBce);
    // #16: edge-h: h = silu(h1@W_ce + b_ce + Um[src] + Ug[dst]); scatter into S_h[dst]
    gemm_mm<false,true,true,true,false,false,false><<<gridE, NTHR, SM_TOTAL>>>(
        pXhi, pXlo, nullptr, nullptr, pWThi + OFF_CE, pWTlo + OFF_CE, nullptr, nullptr,
        pBce, nullptr, DDIM, DDIM, nullptr, nullptr,
        pUm, pUg, pSh, nullptr, nullptr, esrc, edst, E, DDIM);
    // #17-#18: prep emb_w1^T, edge_w1^T
    prep_wT<<<(512 * 512 + 255) / 256, 256>>>(emb_w1, 512, pWThi + OFF_EMBW1, pWTlo + OFF_EMBW1);
    prep_wT<<<(512 * 512 + 255) / 256, 256>>>(edge_w1, 512, pWThi + OFF_EDGEW1, pWTlo + OFF_EDGEW1);
    // #19: badd = emb_b1 + edge_b1
    vec_add<<<2, 256>>>(emb_b1, edge_b1, pBadd);
    // #20-#21: split S_h1 -> X, S_h -> Y   (h1 in X is dead after #16)
    split_pack<<<(unsigned)(((size_t)G * 256 + 255) / 256), 256>>>(pSh1, pXhi, pXlo, (size_t)G * 256);
    split_pack<<<(unsigned)(((size_t)G * 256 + 255) / 256), 256>>>(pSh, pYhi, pYlo, (size_t)G * 256);
    // #22: agg = concat(S_h1,S_h) @ [emb_w1; edge_w1] + cnt*badd -> Z pair
    gemm_mm<true,false,false,false,false,true,true><<<gridG, NTHR, SM_TOTAL>>>(
        pXhi, pXlo, pYhi, pYlo,
        pWThi + OFF_EMBW1, pWTlo + OFF_EMBW1, pWThi + OFF_EDGEW1, pWTlo + OFF_EDGEW1,
        pZb, nullptr, DDIM, DDIM, pZhi, pZlo,
        nullptr, nullptr, nullptr, pCnt, pBadd, nullptr, nullptr, G, 2 * DDIM);
    // #23-#24: prep node_w0 halves
    prep_wT<<<(512 * 512 + 255) / 256, 256>>>(node_w0, 512, pWThi + OFF_N0A, pWTlo + OFF_N0A);
    prep_wT<<<(512 * 512 + 255) / 256, 256>>>(node_w0 + (size_t)512 * 512, 512, pWThi + OFF_N0B, pWTlo + OFF_N0B);
    // #25: h2 = silu(concat(grid, agg) @ node_w0 + node_b0) -> X
    gemm_mm<true,true,false,false,false,true,false><<<gridG, NTHR, SM_TOTAL>>>(
        pGhi, pGlo, pZhi, pZlo,
        pWThi + OFF_N0A, pWTlo + OFF_N0A, pWThi + OFF_N0B, pWTlo + OFF_N0B,
        node_b0, nullptr, DDIM, DDIM, pXhi, pXlo,
        nullptr, nullptr, nullptr, nullptr, nullptr, nullptr, nullptr, G, 2 * DDIM);
    // #26: prep out_w0^T
    prep_wT<<<(512 * 512 + 255) / 256, 256>>>(out_w0, 512, pWThi + OFF_OUTW0, pWTlo + OFF_OUTW0);
    // #27: split node_w1 -> SB
    split_pack<<<(512 * 256 + 255) / 256, 256>>>(node_w1, pSBhi, pSBlo, 512 * 256);
    // #28: W_no^T = (node_w1 @ out_w0)^T
    gemm_mm<false,false,false,false,false,true,false><<<grid512, NTHR, SM_TOTAL>>>(
        pWThi + OFF_OUTW0, pWTlo + OFF_OUTW0, nullptr, nullptr, pSBhi, pSBlo, nullptr, nullptr,
        pZb, nullptr, DDIM, DDIM, pWThi + OFF_NO, pWTlo + OFF_NO,
        nullptr, nullptr, nullptr, nullptr, nullptr, nullptr, nullptr, 512, DDIM);
    // #29: b_no = out_b0 + node_b1 @ out_w0
    bias_fold<<<2, 256>>>(out_b0, node_b1, out_w0, pBno);
    // #30: o1 = silu(concat(grid, h2) @ [out_w0; W_no] + b_no) -> Y
    gemm_mm<true,true,false,false,false,true,false><<<gridG, NTHR, SM_TOTAL>>>(
        pGhi, pGlo, pXhi, pXlo,
        pWThi + OFF_OUTW0, pWTlo + OFF_OUTW0, pWThi + OFF_NO, pWTlo + OFF_NO,
        pBno, nullptr, DDIM, DDIM, pYhi, pYlo,
        nullptr, nullptr, nullptr, nullptr, nullptr, nullptr, nullptr, G, 2 * DDIM);
    // #31: prep out_w1 (padded 471 -> 512)
    prep_wT<<<(512 * 512 + 255) / 256, 256>>>(out_w1, NOUT, pWThi + OFF_OUTW1, pWTlo + OFF_OUTW1);
    // #32: out = o1 @ out_w1 + out_b1 (fp32, N-guard 471)
    gemm_mm<false,false,false,false,true,false,false><<<gridG, NTHR, SM_TOTAL>>>(
        pYhi, pYlo, nullptr, nullptr, pWThi + OFF_OUTW1, pWTlo + OFF_OUTW1, nullptr, nullptr,
        out_b1, out, NOUT, NOUT, nullptr, nullptr,
        nullptr, nullptr, nullptr, nullptr, nullptr, nullptr, nullptr, G, DDIM);
}